// round 1
// baseline (speedup 1.0000x reference)
#include <cuda_runtime.h>
#include <math.h>

#define B_  4
#define T_  2048
#define E_  128
#define H_  8
#define BH_ 32
#define M_  8192      // B*T
#define EH_ 1024      // E*H

// scale^2 = e^-0.5 = 1/sqrt(128)
#define S2_ 0.08838834764831845f

// Scratch (device globals: allowed; runtime alloc is not)
__device__ float Qg[(size_t)BH_ * T_ * E_];   // [bh][t][e]
__device__ float Kg[(size_t)BH_ * T_ * E_];
__device__ float Vg[(size_t)BH_ * T_ * E_];
__device__ float Og[(size_t)M_ * EH_];        // [b*t][h*e]

// ---------------------------------------------------------------------------
// Kernel 1: QKV projection.  X(8192x128) @ W(128x1024) for W in {Wq,Wk,Wv}.
// Output scattered to [bh][t][e] layout. 64x64 tile, 256 threads, 4x4 micro.
// ---------------------------------------------------------------------------
__global__ __launch_bounds__(256) void qkv_kernel(
    const float* __restrict__ x,
    const float* __restrict__ Wq,
    const float* __restrict__ Wk,
    const float* __restrict__ Wv)
{
    __shared__ float As[32][68];   // A tile, transposed: As[k][m]
    __shared__ float Bs[32][68];   // B tile: Bs[k][n]

    const int z = blockIdx.z;
    const float* __restrict__ Wp = (z == 0) ? Wq : (z == 1) ? Wk : Wv;
    float* __restrict__ outp     = (z == 0) ? Qg : (z == 1) ? Kg : Vg;

    const int m0 = blockIdx.x * 64;
    const int n0 = blockIdx.y * 64;
    const int tid = threadIdx.x;
    const int ty = tid >> 4;       // 0..15
    const int tx = tid & 15;       // 0..15

    float acc[4][4];
#pragma unroll
    for (int i = 0; i < 4; i++)
#pragma unroll
        for (int j = 0; j < 4; j++) acc[i][j] = 0.f;

    for (int k0 = 0; k0 < E_; k0 += 32) {
        // A tile (64 rows x 32 k), transposed store
#pragma unroll
        for (int i = 0; i < 2; i++) {
            int f = tid + i * 256;            // 0..511
            int row = f >> 3;                 // 0..63
            int k4  = f & 7;                  // 0..7
            float4 v = *(const float4*)&x[(size_t)(m0 + row) * E_ + k0 + 4 * k4];
            As[4 * k4 + 0][row] = v.x;
            As[4 * k4 + 1][row] = v.y;
            As[4 * k4 + 2][row] = v.z;
            As[4 * k4 + 3][row] = v.w;
        }
        // B tile (32 k x 64 n)
#pragma unroll
        for (int i = 0; i < 2; i++) {
            int f = tid + i * 256;
            int kk = f >> 4;                  // 0..31
            int n4 = f & 15;                  // 0..15
            *(float4*)&Bs[kk][4 * n4] =
                *(const float4*)&Wp[(size_t)(k0 + kk) * EH_ + n0 + 4 * n4];
        }
        __syncthreads();
#pragma unroll
        for (int kk = 0; kk < 32; kk++) {
            float4 a = *(const float4*)&As[kk][4 * ty];
            float4 b = *(const float4*)&Bs[kk][4 * tx];
            float av[4] = {a.x, a.y, a.z, a.w};
            float bv[4] = {b.x, b.y, b.z, b.w};
#pragma unroll
            for (int i = 0; i < 4; i++)
#pragma unroll
                for (int j = 0; j < 4; j++) acc[i][j] += av[i] * bv[j];
        }
        __syncthreads();
    }

    // scatter: row m = b*T + t ; col n = h*E + e  ->  [(b*H+h)*T + t]*E + e
    const int nbase = n0 + 4 * tx;
    const int h = nbase >> 7;          // constant within 64-wide tile
    const int e0 = nbase & 127;        // multiple of 4
#pragma unroll
    for (int i = 0; i < 4; i++) {
        int m = m0 + 4 * ty + i;
        int b = m >> 11;
        int t = m & 2047;
        size_t base = ((size_t)(b * H_ + h) * T_ + t) * E_ + e0;
        float4 v = make_float4(acc[i][0], acc[i][1], acc[i][2], acc[i][3]);
        *(float4*)&outp[base] = v;
    }
}

// ---------------------------------------------------------------------------
// Kernel 2: flash attention. BM=BN=32, D=128, 256 threads.
// grid = (64 qtiles, 32 bh). Static smem < 48KB.
// ---------------------------------------------------------------------------
__global__ __launch_bounds__(256) void attn_kernel(const int* __restrict__ mask)
{
    __shared__ float Qs[32][129];      // scalar access, odd stride
    __shared__ float KVbuf[32 * 132];  // K uses stride 129, V uses stride 132
    __shared__ float Ss[32][33];       // scores / probabilities
    __shared__ float arow[32];
    __shared__ float lrow[32];
    __shared__ int   needb;

    const int bh = blockIdx.y;
    const int qt = blockIdx.x;
    const int q0 = qt * 32;
    const int tid = threadIdx.x;
    const int ty = tid >> 4, tx = tid & 15;     // S gemm layout (16x16, 2x2 micro)
    const int orow = tid >> 3;                  // O layout: 32 rows x 8 col-groups
    const int oc0  = (tid & 7) * 16;

    const float* __restrict__ Qp = Qg + (size_t)bh * T_ * E_;
    const float* __restrict__ Kp = Kg + (size_t)bh * T_ * E_;
    const float* __restrict__ Vp = Vg + (size_t)bh * T_ * E_;

    // Load Q tile (32 x 128)
#pragma unroll
    for (int i = 0; i < 16; i++) {
        int f = tid + i * 256;         // 0..4095
        int row = f >> 7, c = f & 127;
        Qs[row][c] = Qp[(size_t)(q0 + row) * E_ + c];
    }

    float o[16];
#pragma unroll
    for (int j = 0; j < 16; j++) o[j] = 0.f;

    float m_i = -INFINITY;   // valid in tid<32 (softmax warp), row = tid
    float l_i = 0.f;

    const int ntA = qt + 1;  // causal tiles

    for (int kt = 0; kt < ntA; kt++) {
        const int kt0 = kt * 32;
        __syncthreads();   // prev O-update done before overwriting KV / Ss

        // Load K tile: stride 129
#pragma unroll
        for (int i = 0; i < 16; i++) {
            int f = tid + i * 256;
            int row = f >> 7, c = f & 127;
            KVbuf[row * 129 + c] = Kp[(size_t)(kt0 + row) * E_ + c];
        }
        __syncthreads();

        // S = Q K^T (2x2 micro per thread) + masking
        {
            const int r0 = 2 * ty, c0 = 2 * tx;
            float a00 = 0.f, a01 = 0.f, a10 = 0.f, a11 = 0.f;
#pragma unroll 8
            for (int k = 0; k < 128; k++) {
                float qa = Qs[r0][k];
                float qb = Qs[r0 + 1][k];
                float ka = KVbuf[c0 * 129 + k];
                float kb = KVbuf[(c0 + 1) * 129 + k];
                a00 += qa * ka; a01 += qa * kb;
                a10 += qb * ka; a11 += qb * kb;
            }
            float av[2][2] = {{a00, a01}, {a10, a11}};
#pragma unroll
            for (int i = 0; i < 2; i++)
#pragma unroll
                for (int j = 0; j < 2; j++) {
                    int q = q0 + r0 + i;
                    int k = kt0 + c0 + j;
                    float s = av[i][j] * S2_;
                    if (k > q) s = -INFINITY;
                    if (mask[(size_t)q * T_ + k] == 0) s = -1e9f;
                    Ss[r0 + i][c0 + j] = s;
                }
        }
        __syncthreads();

        // warp0: online softmax on Ss; warps 1-7: load V tile (stride 132)
        if (tid < 32) {
            const int r = tid;
            float mt = -INFINITY;
#pragma unroll
            for (int c = 0; c < 32; c++) mt = fmaxf(mt, Ss[r][c]);
            float mn = fmaxf(m_i, mt);
            float alpha = __expf(m_i - mn);
            float lsum = 0.f;
#pragma unroll
            for (int c = 0; c < 32; c++) {
                float p = __expf(Ss[r][c] - mn);
                Ss[r][c] = p;
                lsum += p;
            }
            l_i = l_i * alpha + lsum;
            m_i = mn;
            arow[r] = alpha;
        } else {
            for (int f = tid - 32; f < 1024; f += 224) {
                int row = f >> 5, c4 = f & 31;
                *(float4*)&KVbuf[row * 132 + 4 * c4] =
                    *(const float4*)&Vp[(size_t)(kt0 + row) * E_ + 4 * c4];
            }
        }
        __syncthreads();

        // O += P @ V
        {
            float al = arow[orow];
#pragma unroll
            for (int j = 0; j < 16; j++) o[j] *= al;
            for (int kk = 0; kk < 32; kk++) {
                float p = Ss[orow][kk];
                if (p != 0.f) {
                    const float* vr = &KVbuf[kk * 132 + oc0];
#pragma unroll
                    for (int j4 = 0; j4 < 4; j4++) {
                        float4 v = *(const float4*)&vr[4 * j4];
                        o[4 * j4 + 0] += p * v.x;
                        o[4 * j4 + 1] += p * v.y;
                        o[4 * j4 + 2] += p * v.z;
                        o[4 * j4 + 3] += p * v.w;
                    }
                }
            }
        }
    }

    // Does any row need the future (mask-only) tiles?  (row max still <= -1e9)
    __syncthreads();
    if (tid < 32) {
        int nb = __any_sync(0xffffffffu, m_i < -1e8f);
        if (tid == 0) needb = nb;
    }
    __syncthreads();

    if (needb) {
        for (int kt = ntA; kt < 64; kt++) {
            const int kt0 = kt * 32;
            __syncthreads();
            // V tile (all threads)
            for (int f = tid; f < 1024; f += 256) {
                int row = f >> 5, c4 = f & 31;
                *(float4*)&KVbuf[row * 132 + 4 * c4] =
                    *(const float4*)&Vp[(size_t)(kt0 + row) * E_ + 4 * c4];
            }
            // scores are pure mask constants
#pragma unroll
            for (int i = 0; i < 4; i++) {
                int f = tid + i * 256;
                int r = f >> 5, c = f & 31;
                int q = q0 + r, k = kt0 + c;
                Ss[r][c] = (mask[(size_t)q * T_ + k] == 0) ? -1e9f : -INFINITY;
            }
            __syncthreads();
            if (tid < 32) {
                const int r = tid;
                float mt = -INFINITY;
#pragma unroll
                for (int c = 0; c < 32; c++) mt = fmaxf(mt, Ss[r][c]);
                float mn = fmaxf(m_i, mt);
                float alpha = __expf(m_i - mn);
                float lsum = 0.f;
#pragma unroll
                for (int c = 0; c < 32; c++) {
                    float p = __expf(Ss[r][c] - mn);
                    Ss[r][c] = p;
                    lsum += p;
                }
                l_i = l_i * alpha + lsum;
                m_i = mn;
                arow[r] = alpha;
            }
            __syncthreads();
            {
                float al = arow[orow];
#pragma unroll
                for (int j = 0; j < 16; j++) o[j] *= al;
                for (int kk = 0; kk < 32; kk++) {
                    float p = Ss[orow][kk];
                    if (p != 0.f) {
                        const float* vr = &KVbuf[kk * 132 + oc0];
#pragma unroll
                        for (int j4 = 0; j4 < 4; j4++) {
                            float4 v = *(const float4*)&vr[4 * j4];
                            o[4 * j4 + 0] += p * v.x;
                            o[4 * j4 + 1] += p * v.y;
                            o[4 * j4 + 2] += p * v.z;
                            o[4 * j4 + 3] += p * v.w;
                        }
                    }
                }
            }
        }
    }

    __syncthreads();
    if (tid < 32) lrow[tid] = l_i;
    __syncthreads();

    const float inv = 1.0f / lrow[orow];
    const int b = bh >> 3, h = bh & 7;
    size_t base = ((size_t)(b * T_ + q0 + orow)) * EH_ + h * E_ + oc0;
#pragma unroll
    for (int j4 = 0; j4 < 4; j4++) {
        float4 v = make_float4(o[4 * j4 + 0] * inv, o[4 * j4 + 1] * inv,
                               o[4 * j4 + 2] * inv, o[4 * j4 + 3] * inv);
        *(float4*)&Og[base + 4 * j4] = v;
    }
}

// ---------------------------------------------------------------------------
// Kernel 3: output projection. Og(8192x1024) @ Wu(1024x128) + bu.
// ---------------------------------------------------------------------------
__global__ __launch_bounds__(256) void out_kernel(
    const float* __restrict__ Wu,
    const float* __restrict__ bu,
    float* __restrict__ out)
{
    __shared__ float As[32][68];
    __shared__ float Bs[32][68];

    const int m0 = blockIdx.x * 64;
    const int n0 = blockIdx.y * 64;
    const int tid = threadIdx.x;
    const int ty = tid >> 4, tx = tid & 15;

    float acc[4][4];
#pragma unroll
    for (int i = 0; i < 4; i++)
#pragma unroll
        for (int j = 0; j < 4; j++) acc[i][j] = 0.f;

    for (int k0 = 0; k0 < EH_; k0 += 32) {
#pragma unroll
        for (int i = 0; i < 2; i++) {
            int f = tid + i * 256;
            int row = f >> 3;
            int k4  = f & 7;
            float4 v = *(const float4*)&Og[(size_t)(m0 + row) * EH_ + k0 + 4 * k4];
            As[4 * k4 + 0][row] = v.x;
            As[4 * k4 + 1][row] = v.y;
            As[4 * k4 + 2][row] = v.z;
            As[4 * k4 + 3][row] = v.w;
        }
#pragma unroll
        for (int i = 0; i < 2; i++) {
            int f = tid + i * 256;
            int kk = f >> 4;
            int n4 = f & 15;
            *(float4*)&Bs[kk][4 * n4] =
                *(const float4*)&Wu[(size_t)(k0 + kk) * E_ + n0 + 4 * n4];
        }
        __syncthreads();
#pragma unroll
        for (int kk = 0; kk < 32; kk++) {
            float4 a = *(const float4*)&As[kk][4 * ty];
            float4 b = *(const float4*)&Bs[kk][4 * tx];
            float av[4] = {a.x, a.y, a.z, a.w};
            float bv[4] = {b.x, b.y, b.z, b.w};
#pragma unroll
            for (int i = 0; i < 4; i++)
#pragma unroll
                for (int j = 0; j < 4; j++) acc[i][j] += av[i] * bv[j];
        }
        __syncthreads();
    }

    const int n = n0 + 4 * tx;
    float4 bias = *(const float4*)&bu[n];
#pragma unroll
    for (int i = 0; i < 4; i++) {
        int m = m0 + 4 * ty + i;
        float4 v = make_float4(acc[i][0] + bias.x, acc[i][1] + bias.y,
                               acc[i][2] + bias.z, acc[i][3] + bias.w);
        *(float4*)&out[(size_t)m * E_ + n] = v;
    }
}

// ---------------------------------------------------------------------------
extern "C" void kernel_launch(void* const* d_in, const int* in_sizes, int n_in,
                              void* d_out, int out_size)
{
    const float* x   = (const float*)d_in[0];
    const int*  mask = (const int*)  d_in[1];
    const float* Wq  = (const float*)d_in[2];
    const float* Wk  = (const float*)d_in[3];
    const float* Wv  = (const float*)d_in[4];
    const float* Wu  = (const float*)d_in[5];
    const float* bu  = (const float*)d_in[6];
    float* out = (float*)d_out;

    qkv_kernel<<<dim3(M_ / 64, EH_ / 64, 3), 256>>>(x, Wq, Wk, Wv);
    attn_kernel<<<dim3(T_ / 32, BH_), 256>>>(mask);
    out_kernel<<<dim3(M_ / 64, E_ / 64), 256>>>(Wu, bu, out);
}

// round 2
// speedup vs baseline: 1.4283x; 1.4283x over previous
#include <cuda_runtime.h>
#include <math.h>

#define B_  4
#define T_  2048
#define E_  128
#define H_  8
#define BH_ 32
#define M_  8192      // B*T
#define EH_ 1024      // E*H

// scale^2 = e^-0.5 = 1/sqrt(128)
#define S2_ 0.08838834764831845f

// Attention tile config
#define BM_ 64
#define BN_ 64
#define SQ_ 132      // Q / KV smem row stride (floats)
#define SS_ 65       // score smem row stride (floats)

// dynamic smem: Qs + KV + Ss + arow + lrow + needb
#define SMEM_ATTN ((2 * BM_ * SQ_ + BM_ * SS_ + BM_ + BM_) * 4 + 16)

// Scratch (device globals: allowed; runtime alloc is not)
__device__ float Qg[(size_t)BH_ * T_ * E_];   // [bh][t][e]
__device__ float Kg[(size_t)BH_ * T_ * E_];
__device__ float Vg[(size_t)BH_ * T_ * E_];
__device__ float Og[(size_t)M_ * EH_];        // [b*t][h*e]

// ---------------------------------------------------------------------------
// Kernel 1: QKV projection.  X(8192x128) @ W(128x1024) for W in {Wq,Wk,Wv}.
// Output scattered to [bh][t][e] layout. 64x64 tile, 256 threads, 4x4 micro.
// ---------------------------------------------------------------------------
__global__ __launch_bounds__(256) void qkv_kernel(
    const float* __restrict__ x,
    const float* __restrict__ Wq,
    const float* __restrict__ Wk,
    const float* __restrict__ Wv)
{
    __shared__ float As[32][68];   // A tile, transposed: As[k][m]
    __shared__ float Bs[32][68];   // B tile: Bs[k][n]

    const int z = blockIdx.z;
    const float* __restrict__ Wp = (z == 0) ? Wq : (z == 1) ? Wk : Wv;
    float* __restrict__ outp     = (z == 0) ? Qg : (z == 1) ? Kg : Vg;

    const int m0 = blockIdx.x * 64;
    const int n0 = blockIdx.y * 64;
    const int tid = threadIdx.x;
    const int ty = tid >> 4;       // 0..15
    const int tx = tid & 15;       // 0..15

    float acc[4][4];
#pragma unroll
    for (int i = 0; i < 4; i++)
#pragma unroll
        for (int j = 0; j < 4; j++) acc[i][j] = 0.f;

    for (int k0 = 0; k0 < E_; k0 += 32) {
#pragma unroll
        for (int i = 0; i < 2; i++) {
            int f = tid + i * 256;            // 0..511
            int row = f >> 3;                 // 0..63
            int k4  = f & 7;                  // 0..7
            float4 v = *(const float4*)&x[(size_t)(m0 + row) * E_ + k0 + 4 * k4];
            As[4 * k4 + 0][row] = v.x;
            As[4 * k4 + 1][row] = v.y;
            As[4 * k4 + 2][row] = v.z;
            As[4 * k4 + 3][row] = v.w;
        }
#pragma unroll
        for (int i = 0; i < 2; i++) {
            int f = tid + i * 256;
            int kk = f >> 4;                  // 0..31
            int n4 = f & 15;                  // 0..15
            *(float4*)&Bs[kk][4 * n4] =
                *(const float4*)&Wp[(size_t)(k0 + kk) * EH_ + n0 + 4 * n4];
        }
        __syncthreads();
#pragma unroll
        for (int kk = 0; kk < 32; kk++) {
            float4 a = *(const float4*)&As[kk][4 * ty];
            float4 b = *(const float4*)&Bs[kk][4 * tx];
            float av[4] = {a.x, a.y, a.z, a.w};
            float bv[4] = {b.x, b.y, b.z, b.w};
#pragma unroll
            for (int i = 0; i < 4; i++)
#pragma unroll
                for (int j = 0; j < 4; j++) acc[i][j] += av[i] * bv[j];
        }
        __syncthreads();
    }

    const int nbase = n0 + 4 * tx;
    const int h = nbase >> 7;
    const int e0 = nbase & 127;
#pragma unroll
    for (int i = 0; i < 4; i++) {
        int m = m0 + 4 * ty + i;
        int b = m >> 11;
        int t = m & 2047;
        size_t base = ((size_t)(b * H_ + h) * T_ + t) * E_ + e0;
        float4 v = make_float4(acc[i][0], acc[i][1], acc[i][2], acc[i][3]);
        *(float4*)&outp[base] = v;
    }
}

// ---------------------------------------------------------------------------
// Kernel 2: flash attention v2. BM=BN=64, D=128, 256 threads, dynamic smem.
// S-gemm: 16x16 thread grid, 4x4 micro, k-chunks of 4 via float4.
// O-update: each thread owns 4 rows x 8 cols of O (32 accum regs).
// ---------------------------------------------------------------------------
__global__ __launch_bounds__(256, 2) void attn_kernel(const int* __restrict__ mask)
{
    extern __shared__ float sm[];
    float* Qs   = sm;                       // [64][132]
    float* KV   = Qs + BM_ * SQ_;           // [64][132]  (K then V)
    float* Ss   = KV + BM_ * SQ_;           // [64][65]
    float* arow = Ss + BM_ * SS_;           // [64]
    float* lrow = arow + BM_;               // [64]
    int*   needb = (int*)(lrow + BM_);

    const int bh = blockIdx.y;
    const int qt = (gridDim.x - 1) - blockIdx.x;   // heavy blocks first
    const int q0 = qt * BM_;
    const int tid = threadIdx.x;
    const int ty = tid >> 4, tx = tid & 15;
    const int r0 = 4 * ty, c0 = 4 * tx;     // S-gemm micro-tile origin
    const int orow = 4 * (tid >> 4);        // O: rows orow..orow+3
    const int oc0  = 8 * (tid & 15);        // O: cols oc0..oc0+7

    const float* __restrict__ Qp = Qg + (size_t)bh * T_ * E_;
    const float* __restrict__ Kp = Kg + (size_t)bh * T_ * E_;
    const float* __restrict__ Vp = Vg + (size_t)bh * T_ * E_;

    // Load Q tile (64 x 128), pre-scaled by e^-0.5
#pragma unroll
    for (int i = 0; i < 8; i++) {
        int f = tid + i * 256;              // 0..2047 float4 slots
        int row = f >> 5, c4 = f & 31;
        float4 v = *(const float4*)&Qp[(size_t)(q0 + row) * E_ + 4 * c4];
        v.x *= S2_; v.y *= S2_; v.z *= S2_; v.w *= S2_;
        *(float4*)&Qs[row * SQ_ + 4 * c4] = v;
    }

    float o[32];
#pragma unroll
    for (int j = 0; j < 32; j++) o[j] = 0.f;

    float m_i = -INFINITY;   // valid in tid<64 (softmax threads), row = tid
    float l_i = 0.f;

    const int ntA = qt + 1;  // causal tiles

    for (int kt = 0; kt < ntA; kt++) {
        const int kt0 = kt * BN_;
        __syncthreads();   // prev O-update done before overwriting KV / Ss

        // Load K tile
#pragma unroll
        for (int i = 0; i < 8; i++) {
            int f = tid + i * 256;
            int row = f >> 5, c4 = f & 31;
            *(float4*)&KV[row * SQ_ + 4 * c4] =
                *(const float4*)&Kp[(size_t)(kt0 + row) * E_ + 4 * c4];
        }
        __syncthreads();

        // S = Q K^T  (4x4 micro, k-chunks of 4)
        {
            float acc[4][4];
#pragma unroll
            for (int i = 0; i < 4; i++)
#pragma unroll
                for (int j = 0; j < 4; j++) acc[i][j] = 0.f;

#pragma unroll 4
            for (int kc = 0; kc < 32; kc++) {
                float4 qa[4], kb[4];
#pragma unroll
                for (int i = 0; i < 4; i++)
                    qa[i] = *(const float4*)&Qs[(r0 + i) * SQ_ + 4 * kc];
#pragma unroll
                for (int j = 0; j < 4; j++)
                    kb[j] = *(const float4*)&KV[(c0 + j) * SQ_ + 4 * kc];
#pragma unroll
                for (int i = 0; i < 4; i++)
#pragma unroll
                    for (int j = 0; j < 4; j++) {
                        acc[i][j] += qa[i].x * kb[j].x;
                        acc[i][j] += qa[i].y * kb[j].y;
                        acc[i][j] += qa[i].z * kb[j].z;
                        acc[i][j] += qa[i].w * kb[j].w;
                    }
            }
            // masks + store
#pragma unroll
            for (int i = 0; i < 4; i++) {
                int q = q0 + r0 + i;
                int4 mrow = *(const int4*)&mask[(size_t)q * T_ + kt0 + c0];
                int mv[4] = {mrow.x, mrow.y, mrow.z, mrow.w};
#pragma unroll
                for (int j = 0; j < 4; j++) {
                    int k = kt0 + c0 + j;
                    float s = acc[i][j];
                    if (k > q) s = -INFINITY;
                    if (mv[j] == 0) s = -1e9f;
                    Ss[(r0 + i) * SS_ + c0 + j] = s;
                }
            }
        }
        __syncthreads();

        // threads 0-63: online softmax; threads 64-255: load V tile
        if (tid < 64) {
            const int r = tid;
            float mt = -INFINITY;
#pragma unroll
            for (int c = 0; c < 64; c++) mt = fmaxf(mt, Ss[r * SS_ + c]);
            float mn = fmaxf(m_i, mt);
            float alpha = __expf(m_i - mn);
            float lsum = 0.f;
#pragma unroll
            for (int c = 0; c < 64; c++) {
                float p = __expf(Ss[r * SS_ + c] - mn);
                Ss[r * SS_ + c] = p;
                lsum += p;
            }
            l_i = l_i * alpha + lsum;
            m_i = mn;
            arow[r] = alpha;
        } else {
            for (int f = tid - 64; f < 2048; f += 192) {
                int row = f >> 5, c4 = f & 31;
                *(float4*)&KV[row * SQ_ + 4 * c4] =
                    *(const float4*)&Vp[(size_t)(kt0 + row) * E_ + 4 * c4];
            }
        }
        __syncthreads();

        // O = O*alpha + P @ V
        {
            float al[4];
#pragma unroll
            for (int i = 0; i < 4; i++) al[i] = arow[orow + i];
#pragma unroll
            for (int i = 0; i < 4; i++)
#pragma unroll
                for (int j = 0; j < 8; j++) o[i * 8 + j] *= al[i];

#pragma unroll 4
            for (int kk = 0; kk < 64; kk++) {
                float p[4];
#pragma unroll
                for (int i = 0; i < 4; i++) p[i] = Ss[(orow + i) * SS_ + kk];
                float4 v0 = *(const float4*)&KV[kk * SQ_ + oc0];
                float4 v1 = *(const float4*)&KV[kk * SQ_ + oc0 + 4];
                float vv[8] = {v0.x, v0.y, v0.z, v0.w, v1.x, v1.y, v1.z, v1.w};
#pragma unroll
                for (int i = 0; i < 4; i++)
#pragma unroll
                    for (int j = 0; j < 8; j++) o[i * 8 + j] += p[i] * vv[j];
            }
        }
    }

    // Phase B: rows whose entire causal range was masked attend to future
    // mask==0 positions (score -1e9 vs future-unmasked -inf). Rare.
    __syncthreads();
    if (tid == 0) *needb = 0;
    __syncthreads();
    if (tid < 64 && m_i < -1e8f) *needb = 1;
    __syncthreads();

    if (*needb) {
        for (int kt = ntA; kt < T_ / BN_; kt++) {
            const int kt0 = kt * BN_;
            __syncthreads();
            // V tile (all threads)
#pragma unroll
            for (int i = 0; i < 8; i++) {
                int f = tid + i * 256;
                int row = f >> 5, c4 = f & 31;
                *(float4*)&KV[row * SQ_ + 4 * c4] =
                    *(const float4*)&Vp[(size_t)(kt0 + row) * E_ + 4 * c4];
            }
            // scores are pure mask constants
#pragma unroll
            for (int i = 0; i < 4; i++) {
                int q = q0 + r0 + i;
                int4 mrow = *(const int4*)&mask[(size_t)q * T_ + kt0 + c0];
                int mv[4] = {mrow.x, mrow.y, mrow.z, mrow.w};
#pragma unroll
                for (int j = 0; j < 4; j++)
                    Ss[(r0 + i) * SS_ + c0 + j] = (mv[j] == 0) ? -1e9f : -INFINITY;
            }
            __syncthreads();
            if (tid < 64) {
                const int r = tid;
                float mt = -INFINITY;
#pragma unroll
                for (int c = 0; c < 64; c++) mt = fmaxf(mt, Ss[r * SS_ + c]);
                float mn = fmaxf(m_i, mt);
                float alpha = __expf(m_i - mn);
                float lsum = 0.f;
#pragma unroll
                for (int c = 0; c < 64; c++) {
                    float p = __expf(Ss[r * SS_ + c] - mn);
                    Ss[r * SS_ + c] = p;
                    lsum += p;
                }
                l_i = l_i * alpha + lsum;
                m_i = mn;
                arow[r] = alpha;
            }
            __syncthreads();
            {
                float al[4];
#pragma unroll
                for (int i = 0; i < 4; i++) al[i] = arow[orow + i];
#pragma unroll
                for (int i = 0; i < 4; i++)
#pragma unroll
                    for (int j = 0; j < 8; j++) o[i * 8 + j] *= al[i];
#pragma unroll 4
                for (int kk = 0; kk < 64; kk++) {
                    float p[4];
#pragma unroll
                    for (int i = 0; i < 4; i++) p[i] = Ss[(orow + i) * SS_ + kk];
                    float4 v0 = *(const float4*)&KV[kk * SQ_ + oc0];
                    float4 v1 = *(const float4*)&KV[kk * SQ_ + oc0 + 4];
                    float vv[8] = {v0.x, v0.y, v0.z, v0.w, v1.x, v1.y, v1.z, v1.w};
#pragma unroll
                    for (int i = 0; i < 4; i++)
#pragma unroll
                        for (int j = 0; j < 8; j++) o[i * 8 + j] += p[i] * vv[j];
                }
            }
        }
    }

    __syncthreads();
    if (tid < 64) lrow[tid] = l_i;
    __syncthreads();

    const int b = bh >> 3, h = bh & 7;
#pragma unroll
    for (int i = 0; i < 4; i++) {
        float inv = 1.0f / lrow[orow + i];
        size_t base = ((size_t)(b * T_ + q0 + orow + i)) * EH_ + h * E_ + oc0;
        float4 w0 = make_float4(o[i * 8 + 0] * inv, o[i * 8 + 1] * inv,
                                o[i * 8 + 2] * inv, o[i * 8 + 3] * inv);
        float4 w1 = make_float4(o[i * 8 + 4] * inv, o[i * 8 + 5] * inv,
                                o[i * 8 + 6] * inv, o[i * 8 + 7] * inv);
        *(float4*)&Og[base] = w0;
        *(float4*)&Og[base + 4] = w1;
    }
}

// ---------------------------------------------------------------------------
// Kernel 3: output projection. Og(8192x1024) @ Wu(1024x128) + bu.
// ---------------------------------------------------------------------------
__global__ __launch_bounds__(256) void out_kernel(
    const float* __restrict__ Wu,
    const float* __restrict__ bu,
    float* __restrict__ out)
{
    __shared__ float As[32][68];
    __shared__ float Bs[32][68];

    const int m0 = blockIdx.x * 64;
    const int n0 = blockIdx.y * 64;
    const int tid = threadIdx.x;
    const int ty = tid >> 4, tx = tid & 15;

    float acc[4][4];
#pragma unroll
    for (int i = 0; i < 4; i++)
#pragma unroll
        for (int j = 0; j < 4; j++) acc[i][j] = 0.f;

    for (int k0 = 0; k0 < EH_; k0 += 32) {
#pragma unroll
        for (int i = 0; i < 2; i++) {
            int f = tid + i * 256;
            int row = f >> 3;
            int k4  = f & 7;
            float4 v = *(const float4*)&Og[(size_t)(m0 + row) * EH_ + k0 + 4 * k4];
            As[4 * k4 + 0][row] = v.x;
            As[4 * k4 + 1][row] = v.y;
            As[4 * k4 + 2][row] = v.z;
            As[4 * k4 + 3][row] = v.w;
        }
#pragma unroll
        for (int i = 0; i < 2; i++) {
            int f = tid + i * 256;
            int kk = f >> 4;
            int n4 = f & 15;
            *(float4*)&Bs[kk][4 * n4] =
                *(const float4*)&Wu[(size_t)(k0 + kk) * E_ + n0 + 4 * n4];
        }
        __syncthreads();
#pragma unroll
        for (int kk = 0; kk < 32; kk++) {
            float4 a = *(const float4*)&As[kk][4 * ty];
            float4 b = *(const float4*)&Bs[kk][4 * tx];
            float av[4] = {a.x, a.y, a.z, a.w};
            float bv[4] = {b.x, b.y, b.z, b.w};
#pragma unroll
            for (int i = 0; i < 4; i++)
#pragma unroll
                for (int j = 0; j < 4; j++) acc[i][j] += av[i] * bv[j];
        }
        __syncthreads();
    }

    const int n = n0 + 4 * tx;
    float4 bias = *(const float4*)&bu[n];
#pragma unroll
    for (int i = 0; i < 4; i++) {
        int m = m0 + 4 * ty + i;
        float4 v = make_float4(acc[i][0] + bias.x, acc[i][1] + bias.y,
                               acc[i][2] + bias.z, acc[i][3] + bias.w);
        *(float4*)&out[(size_t)m * E_ + n] = v;
    }
}

// ---------------------------------------------------------------------------
extern "C" void kernel_launch(void* const* d_in, const int* in_sizes, int n_in,
                              void* d_out, int out_size)
{
    const float* x   = (const float*)d_in[0];
    const int*  mask = (const int*)  d_in[1];
    const float* Wq  = (const float*)d_in[2];
    const float* Wk  = (const float*)d_in[3];
    const float* Wv  = (const float*)d_in[4];
    const float* Wu  = (const float*)d_in[5];
    const float* bu  = (const float*)d_in[6];
    float* out = (float*)d_out;

    static_assert(SMEM_ATTN < 100 * 1024, "smem");
    cudaFuncSetAttribute(attn_kernel,
                         cudaFuncAttributeMaxDynamicSharedMemorySize, SMEM_ATTN);

    qkv_kernel<<<dim3(M_ / 64, EH_ / 64, 3), 256>>>(x, Wq, Wk, Wv);
    attn_kernel<<<dim3(T_ / BM_, BH_), 256, SMEM_ATTN>>>(mask);
    out_kernel<<<dim3(M_ / 64, E_ / 64), 256>>>(Wu, bu, out);
}

// round 3
// speedup vs baseline: 2.5295x; 1.7710x over previous
#include <cuda_runtime.h>
#include <math.h>

#define B_  4
#define T_  2048
#define E_  128
#define H_  8
#define BH_ 32
#define M_  8192      // B*T
#define EH_ 1024      // E*H

// scale^2 = e^-0.5 = 1/sqrt(128)
#define S2_ 0.08838834764831845f

// Attention tile config
#define BM_ 64
#define BN_ 64
#define SQ_ 132      // Q / V smem row stride (floats)
#define SK_ 68       // K^T smem row stride (floats): Ks[k][n]
#define SS_ 65       // score smem row stride (floats)

// dynamic smem: Qs + Ks/V + Ss + arow + lrow + needb
#define SMEM_ATTN ((BM_ * SQ_ + 128 * SK_ + BM_ * SS_ + 2 * BM_) * 4 + 16)

// Scratch (device globals: allowed; runtime alloc is not)
__device__ float Qg[(size_t)BH_ * T_ * E_];   // [bh][t][e]
__device__ float Kg[(size_t)BH_ * T_ * E_];   // K TRANSPOSED: [bh][e][t]
__device__ float Vg[(size_t)BH_ * T_ * E_];   // [bh][t][e]
__device__ float Og[(size_t)M_ * EH_];        // [b*t][h*e]

// ---------------------------------------------------------------------------
// Kernel 1: QKV projection.  X(8192x128) @ W(128x1024).
// Q,V scattered to [bh][t][e]; K scattered TRANSPOSED to [bh][e][t] via a
// stride-65 smem transpose (conflict <= 2-way both directions).
// ---------------------------------------------------------------------------
__global__ __launch_bounds__(256) void qkv_kernel(
    const float* __restrict__ x,
    const float* __restrict__ Wq,
    const float* __restrict__ Wk,
    const float* __restrict__ Wv)
{
    __shared__ float smbuf[2 * 32 * 68];
    float (*As)[68] = (float(*)[68])smbuf;                // [32][68] A^T: As[k][m]
    float (*Bs)[68] = (float(*)[68])(smbuf + 32 * 68);    // [32][68] Bs[k][n]

    const int z = blockIdx.z;
    const float* __restrict__ Wp = (z == 0) ? Wq : (z == 1) ? Wk : Wv;
    float* __restrict__ outp     = (z == 0) ? Qg : (z == 1) ? Kg : Vg;

    const int m0 = blockIdx.x * 64;
    const int n0 = blockIdx.y * 64;
    const int tid = threadIdx.x;
    const int ty = tid >> 4;       // 0..15
    const int tx = tid & 15;       // 0..15

    float acc[4][4];
#pragma unroll
    for (int i = 0; i < 4; i++)
#pragma unroll
        for (int j = 0; j < 4; j++) acc[i][j] = 0.f;

    for (int k0 = 0; k0 < E_; k0 += 32) {
#pragma unroll
        for (int i = 0; i < 2; i++) {
            int f = tid + i * 256;            // 0..511
            int row = f >> 3;                 // 0..63
            int k4  = f & 7;                  // 0..7
            float4 v = *(const float4*)&x[(size_t)(m0 + row) * E_ + k0 + 4 * k4];
            As[4 * k4 + 0][row] = v.x;
            As[4 * k4 + 1][row] = v.y;
            As[4 * k4 + 2][row] = v.z;
            As[4 * k4 + 3][row] = v.w;
        }
#pragma unroll
        for (int i = 0; i < 2; i++) {
            int f = tid + i * 256;
            int kk = f >> 4;                  // 0..31
            int n4 = f & 15;                  // 0..15
            *(float4*)&Bs[kk][4 * n4] =
                *(const float4*)&Wp[(size_t)(k0 + kk) * EH_ + n0 + 4 * n4];
        }
        __syncthreads();
#pragma unroll
        for (int kk = 0; kk < 32; kk++) {
            float4 a = *(const float4*)&As[kk][4 * ty];
            float4 b = *(const float4*)&Bs[kk][4 * tx];
            float av[4] = {a.x, a.y, a.z, a.w};
            float bv[4] = {b.x, b.y, b.z, b.w};
#pragma unroll
            for (int i = 0; i < 4; i++)
#pragma unroll
                for (int j = 0; j < 4; j++) acc[i][j] += av[i] * bv[j];
        }
        __syncthreads();
    }

    const int b = m0 >> 11, t0 = m0 & 2047;
    const int h = n0 >> 7,  e0 = n0 & 127;

    if (z == 1) {
        // transpose via smem (stride 65, odd: <=2-way conflicts both ways)
        float* Ts = smbuf;   // [64][65], 16640 floats needed <= 4352? no: 64*65=4160 floats, smbuf=4352 ok
#pragma unroll
        for (int i = 0; i < 4; i++)
#pragma unroll
            for (int j = 0; j < 4; j++)
                Ts[(4 * ty + i) * 65 + 4 * tx + j] = acc[i][j];   // [local_m][local_n]
        __syncthreads();
        // write Kgt[bh][e][t]: 64 local_n rows x 64 t (16 float4)
        for (int f = tid; f < 64 * 16; f += 256) {
            int ln = f >> 4;          // local n: 0..63
            int c4 = f & 15;          // float4 along m(t)
            float4 v;
            v.x = Ts[(4 * c4 + 0) * 65 + ln];
            v.y = Ts[(4 * c4 + 1) * 65 + ln];
            v.z = Ts[(4 * c4 + 2) * 65 + ln];
            v.w = Ts[(4 * c4 + 3) * 65 + ln];
            size_t base = ((size_t)((b * H_ + h) * E_ + e0 + ln)) * T_ + t0 + 4 * c4;
            *(float4*)&outp[base] = v;
        }
    } else {
        const int nb = 4 * tx;   // within-head e offset (tile is within one head)
#pragma unroll
        for (int i = 0; i < 4; i++) {
            int t = t0 + 4 * ty + i;
            size_t base = ((size_t)(b * H_ + h) * T_ + t) * E_ + e0 + nb;
            float4 v = make_float4(acc[i][0], acc[i][1], acc[i][2], acc[i][3]);
            *(float4*)&outp[base] = v;
        }
    }
}

// ---------------------------------------------------------------------------
// Kernel 2: flash attention v3. BM=BN=64, D=128, 256 threads, dynamic smem.
// K held transposed in smem (Ks[k][n], stride 68) -> conflict-free S-gemm.
// O-update cols split as {4tx, 64+4tx} -> conflict-free V reads.
// ---------------------------------------------------------------------------
__global__ __launch_bounds__(256, 2) void attn_kernel(const int* __restrict__ mask)
{
    extern __shared__ float sm[];
    float* Qs   = sm;                       // [64][132]
    float* Ks   = Qs + BM_ * SQ_;           // [128][68] = K^T ; V reuses as [64][132]
    float* Ss   = Ks + 128 * SK_;           // [64][65]
    float* arow = Ss + BM_ * SS_;           // [64]
    float* lrow = arow + BM_;               // [64]
    int*   needb = (int*)(lrow + BM_);

    const int bh = blockIdx.y;
    const int qt = (gridDim.x - 1) - blockIdx.x;   // heavy blocks first
    const int q0 = qt * BM_;
    const int tid = threadIdx.x;
    const int ty = tid >> 4, tx = tid & 15;
    const int r0 = 4 * ty, c0 = 4 * tx;     // S-gemm micro-tile origin
    const int orow = 4 * (tid >> 4);        // O: rows orow..orow+3

    const float* __restrict__ Qp = Qg + (size_t)bh * T_ * E_;
    const float* __restrict__ Kp = Kg + (size_t)bh * E_ * T_;  // [e][t]
    const float* __restrict__ Vp = Vg + (size_t)bh * T_ * E_;

    // Load Q tile (64 x 128), pre-scaled by e^-0.5
#pragma unroll
    for (int i = 0; i < 8; i++) {
        int f = tid + i * 256;              // 0..2047 float4 slots
        int row = f >> 5, c4 = f & 31;
        float4 v = *(const float4*)&Qp[(size_t)(q0 + row) * E_ + 4 * c4];
        v.x *= S2_; v.y *= S2_; v.z *= S2_; v.w *= S2_;
        *(float4*)&Qs[row * SQ_ + 4 * c4] = v;
    }

    float o[32];
#pragma unroll
    for (int j = 0; j < 32; j++) o[j] = 0.f;

    float m_i = -INFINITY;   // valid in tid<64 (softmax threads), row = tid
    float l_i = 0.f;

    const int ntA = qt + 1;  // causal tiles

    for (int kt = 0; kt < ntA; kt++) {
        const int kt0 = kt * BN_;
        __syncthreads();   // prev O-update done before overwriting Ks / Ss

        // Load K^T tile: 128 e-rows x 64 t cols from Kgt
#pragma unroll
        for (int i = 0; i < 8; i++) {
            int f = tid + i * 256;          // 0..2047
            int er = f >> 4, c4 = f & 15;
            *(float4*)&Ks[er * SK_ + 4 * c4] =
                *(const float4*)&Kp[(size_t)er * T_ + kt0 + 4 * c4];
        }
        __syncthreads();

        // S = Q K^T  (4x4 micro, conflict-free reads)
        {
            float acc[4][4];
#pragma unroll
            for (int i = 0; i < 4; i++)
#pragma unroll
                for (int j = 0; j < 4; j++) acc[i][j] = 0.f;

#pragma unroll 8
            for (int kc = 0; kc < 32; kc++) {
                float qa[4][4];
#pragma unroll
                for (int i = 0; i < 4; i++) {
                    float4 q = *(const float4*)&Qs[(r0 + i) * SQ_ + 4 * kc];
                    qa[i][0] = q.x; qa[i][1] = q.y; qa[i][2] = q.z; qa[i][3] = q.w;
                }
#pragma unroll
                for (int kk = 0; kk < 4; kk++) {
                    float4 kb = *(const float4*)&Ks[(4 * kc + kk) * SK_ + c0];
                    float bv[4] = {kb.x, kb.y, kb.z, kb.w};
#pragma unroll
                    for (int i = 0; i < 4; i++)
#pragma unroll
                        for (int j = 0; j < 4; j++)
                            acc[i][j] += qa[i][kk] * bv[j];
                }
            }
            // masks + store
#pragma unroll
            for (int i = 0; i < 4; i++) {
                int q = q0 + r0 + i;
                int4 mrow = *(const int4*)&mask[(size_t)q * T_ + kt0 + c0];
                int mv[4] = {mrow.x, mrow.y, mrow.z, mrow.w};
#pragma unroll
                for (int j = 0; j < 4; j++) {
                    int k = kt0 + c0 + j;
                    float s = acc[i][j];
                    if (k > q) s = -INFINITY;
                    if (mv[j] == 0) s = -1e9f;
                    Ss[(r0 + i) * SS_ + c0 + j] = s;
                }
            }
        }
        __syncthreads();

        // threads 0-63: online softmax; threads 64-255: load V tile
        if (tid < 64) {
            const int r = tid;
            float mt = -INFINITY;
#pragma unroll
            for (int c = 0; c < 64; c++) mt = fmaxf(mt, Ss[r * SS_ + c]);
            float mn = fmaxf(m_i, mt);
            float alpha = __expf(m_i - mn);
            float lsum = 0.f;
#pragma unroll
            for (int c = 0; c < 64; c++) {
                float p = __expf(Ss[r * SS_ + c] - mn);
                Ss[r * SS_ + c] = p;
                lsum += p;
            }
            l_i = l_i * alpha + lsum;
            m_i = mn;
            arow[r] = alpha;
        } else {
            for (int f = tid - 64; f < 2048; f += 192) {
                int row = f >> 5, c4 = f & 31;
                *(float4*)&Ks[row * SQ_ + 4 * c4] =
                    *(const float4*)&Vp[(size_t)(kt0 + row) * E_ + 4 * c4];
            }
        }
        __syncthreads();

        // O = O*alpha + P @ V   (cols {4tx..+3} and {64+4tx..+3})
        {
            float al[4];
#pragma unroll
            for (int i = 0; i < 4; i++) al[i] = arow[orow + i];
#pragma unroll
            for (int i = 0; i < 4; i++)
#pragma unroll
                for (int j = 0; j < 8; j++) o[i * 8 + j] *= al[i];

#pragma unroll 4
            for (int kk = 0; kk < 64; kk++) {
                float p[4];
#pragma unroll
                for (int i = 0; i < 4; i++) p[i] = Ss[(orow + i) * SS_ + kk];
                float4 v0 = *(const float4*)&Ks[kk * SQ_ + 4 * tx];
                float4 v1 = *(const float4*)&Ks[kk * SQ_ + 64 + 4 * tx];
                float vv[8] = {v0.x, v0.y, v0.z, v0.w, v1.x, v1.y, v1.z, v1.w};
#pragma unroll
                for (int i = 0; i < 4; i++)
#pragma unroll
                    for (int j = 0; j < 8; j++) o[i * 8 + j] += p[i] * vv[j];
            }
        }
    }

    // Phase B: rows whose entire causal range was masked attend to future
    // mask==0 positions (score -1e9 vs future-unmasked -inf). Rare.
    __syncthreads();
    if (tid == 0) *needb = 0;
    __syncthreads();
    if (tid < 64 && m_i < -1e8f) *needb = 1;
    __syncthreads();

    if (*needb) {
        for (int kt = ntA; kt < T_ / BN_; kt++) {
            const int kt0 = kt * BN_;
            __syncthreads();
            // V tile (all threads)
#pragma unroll
            for (int i = 0; i < 8; i++) {
                int f = tid + i * 256;
                int row = f >> 5, c4 = f & 31;
                *(float4*)&Ks[row * SQ_ + 4 * c4] =
                    *(const float4*)&Vp[(size_t)(kt0 + row) * E_ + 4 * c4];
            }
            // scores are pure mask constants
#pragma unroll
            for (int i = 0; i < 4; i++) {
                int q = q0 + r0 + i;
                int4 mrow = *(const int4*)&mask[(size_t)q * T_ + kt0 + c0];
                int mv[4] = {mrow.x, mrow.y, mrow.z, mrow.w};
#pragma unroll
                for (int j = 0; j < 4; j++)
                    Ss[(r0 + i) * SS_ + c0 + j] = (mv[j] == 0) ? -1e9f : -INFINITY;
            }
            __syncthreads();
            if (tid < 64) {
                const int r = tid;
                float mt = -INFINITY;
#pragma unroll
                for (int c = 0; c < 64; c++) mt = fmaxf(mt, Ss[r * SS_ + c]);
                float mn = fmaxf(m_i, mt);
                float alpha = __expf(m_i - mn);
                float lsum = 0.f;
#pragma unroll
                for (int c = 0; c < 64; c++) {
                    float p = __expf(Ss[r * SS_ + c] - mn);
                    Ss[r * SS_ + c] = p;
                    lsum += p;
                }
                l_i = l_i * alpha + lsum;
                m_i = mn;
                arow[r] = alpha;
            }
            __syncthreads();
            {
                float al[4];
#pragma unroll
                for (int i = 0; i < 4; i++) al[i] = arow[orow + i];
#pragma unroll
                for (int i = 0; i < 4; i++)
#pragma unroll
                    for (int j = 0; j < 8; j++) o[i * 8 + j] *= al[i];
#pragma unroll 4
                for (int kk = 0; kk < 64; kk++) {
                    float p[4];
#pragma unroll
                    for (int i = 0; i < 4; i++) p[i] = Ss[(orow + i) * SS_ + kk];
                    float4 v0 = *(const float4*)&Ks[kk * SQ_ + 4 * tx];
                    float4 v1 = *(const float4*)&Ks[kk * SQ_ + 64 + 4 * tx];
                    float vv[8] = {v0.x, v0.y, v0.z, v0.w, v1.x, v1.y, v1.z, v1.w};
#pragma unroll
                    for (int i = 0; i < 4; i++)
#pragma unroll
                        for (int j = 0; j < 8; j++) o[i * 8 + j] += p[i] * vv[j];
                }
            }
        }
    }

    __syncthreads();
    if (tid < 64) lrow[tid] = l_i;
    __syncthreads();

    const int b = bh >> 3, h = bh & 7;
#pragma unroll
    for (int i = 0; i < 4; i++) {
        float inv = 1.0f / lrow[orow + i];
        size_t base = ((size_t)(b * T_ + q0 + orow + i)) * EH_ + h * E_;
        float4 w0 = make_float4(o[i * 8 + 0] * inv, o[i * 8 + 1] * inv,
                                o[i * 8 + 2] * inv, o[i * 8 + 3] * inv);
        float4 w1 = make_float4(o[i * 8 + 4] * inv, o[i * 8 + 5] * inv,
                                o[i * 8 + 6] * inv, o[i * 8 + 7] * inv);
        *(float4*)&Og[base + 4 * tx] = w0;
        *(float4*)&Og[base + 64 + 4 * tx] = w1;
    }
}

// ---------------------------------------------------------------------------
// Kernel 3: output projection. Og(8192x1024) @ Wu(1024x128) + bu.
// ---------------------------------------------------------------------------
__global__ __launch_bounds__(256) void out_kernel(
    const float* __restrict__ Wu,
    const float* __restrict__ bu,
    float* __restrict__ out)
{
    __shared__ float As[32][68];
    __shared__ float Bs[32][68];

    const int m0 = blockIdx.x * 64;
    const int n0 = blockIdx.y * 64;
    const int tid = threadIdx.x;
    const int ty = tid >> 4, tx = tid & 15;

    float acc[4][4];
#pragma unroll
    for (int i = 0; i < 4; i++)
#pragma unroll
        for (int j = 0; j < 4; j++) acc[i][j] = 0.f;

    for (int k0 = 0; k0 < EH_; k0 += 32) {
#pragma unroll
        for (int i = 0; i < 2; i++) {
            int f = tid + i * 256;
            int row = f >> 3;
            int k4  = f & 7;
            float4 v = *(const float4*)&Og[(size_t)(m0 + row) * EH_ + k0 + 4 * k4];
            As[4 * k4 + 0][row] = v.x;
            As[4 * k4 + 1][row] = v.y;
            As[4 * k4 + 2][row] = v.z;
            As[4 * k4 + 3][row] = v.w;
        }
#pragma unroll
        for (int i = 0; i < 2; i++) {
            int f = tid + i * 256;
            int kk = f >> 4;
            int n4 = f & 15;
            *(float4*)&Bs[kk][4 * n4] =
                *(const float4*)&Wu[(size_t)(k0 + kk) * E_ + n0 + 4 * n4];
        }
        __syncthreads();
#pragma unroll
        for (int kk = 0; kk < 32; kk++) {
            float4 a = *(const float4*)&As[kk][4 * ty];
            float4 b = *(const float4*)&Bs[kk][4 * tx];
            float av[4] = {a.x, a.y, a.z, a.w};
            float bv[4] = {b.x, b.y, b.z, b.w};
#pragma unroll
            for (int i = 0; i < 4; i++)
#pragma unroll
                for (int j = 0; j < 4; j++) acc[i][j] += av[i] * bv[j];
        }
        __syncthreads();
    }

    const int n = n0 + 4 * tx;
    float4 bias = *(const float4*)&bu[n];
#pragma unroll
    for (int i = 0; i < 4; i++) {
        int m = m0 + 4 * ty + i;
        float4 v = make_float4(acc[i][0] + bias.x, acc[i][1] + bias.y,
                               acc[i][2] + bias.z, acc[i][3] + bias.w);
        *(float4*)&out[(size_t)m * E_ + n] = v;
    }
}

// ---------------------------------------------------------------------------
extern "C" void kernel_launch(void* const* d_in, const int* in_sizes, int n_in,
                              void* d_out, int out_size)
{
    const float* x   = (const float*)d_in[0];
    const int*  mask = (const int*)  d_in[1];
    const float* Wq  = (const float*)d_in[2];
    const float* Wk  = (const float*)d_in[3];
    const float* Wv  = (const float*)d_in[4];
    const float* Wu  = (const float*)d_in[5];
    const float* bu  = (const float*)d_in[6];
    float* out = (float*)d_out;

    static_assert(SMEM_ATTN < 110 * 1024, "smem");
    cudaFuncSetAttribute(attn_kernel,
                         cudaFuncAttributeMaxDynamicSharedMemorySize, SMEM_ATTN);

    qkv_kernel<<<dim3(M_ / 64, EH_ / 64, 3), 256>>>(x, Wq, Wk, Wv);
    attn_kernel<<<dim3(T_ / BM_, BH_), 256, SMEM_ATTN>>>(mask);
    out_kernel<<<dim3(M_ / 64, E_ / 64), 256>>>(Wu, bu, out);
}

// round 6
// speedup vs baseline: 2.8317x; 1.1195x over previous
#include <cuda_runtime.h>
#include <math.h>
#include <stdint.h>

#define B_  4
#define T_  2048
#define E_  128
#define H_  8
#define BH_ 32
#define M_  8192      // B*T
#define EH_ 1024      // E*H

// scale^2 = e^-0.5 = 1/sqrt(128)
#define S2_ 0.08838834764831845f

// Attention tile config
#define BM_ 64
#define BN_ 64
#define SQ_ 132      // Q / V smem row stride (floats)
#define SK_ 68       // K^T smem row stride (floats): Ks[k][n]
#define SS_ 65       // score smem row stride (floats)
#define SMEM_ATTN ((BM_ * SQ_ + 128 * SK_ + BM_ * SS_ + 2 * BM_) * 4 + 16)

// GEMM smem layout (floats): As[128][36], Bs[32][136]; K-transpose stage [128][132]
#define GA_STR 36
#define GB_STR 136
#define G_AS_FLOATS (128 * GA_STR)
#define G_BS_FLOATS (32 * GB_STR)
#define SMEM_QKV (128 * 132 * 4)                      // 67584 B (>= As+Bs)
#define SMEM_OUT ((G_AS_FLOATS + G_BS_FLOATS) * 4)    // 35840 B

// Scratch (device globals: allowed; runtime alloc is not)
__device__ float Qg[(size_t)BH_ * T_ * E_];   // [bh][t][e]
__device__ float Kg[(size_t)BH_ * T_ * E_];   // K TRANSPOSED: [bh][e][t]
__device__ float Vg[(size_t)BH_ * T_ * E_];   // [bh][t][e]
__device__ float Og[(size_t)M_ * EH_];        // [b*t][h*e]

// ---------------------------------------------------------------------------
// mma.sync tf32 helpers (sm_80+, no arch-feature suffix needed)
// ---------------------------------------------------------------------------
__device__ __forceinline__ uint32_t f2tf32(float f) {
    uint32_t r;
    asm("cvt.rna.tf32.f32 %0, %1;" : "=r"(r) : "f"(f));
    return r;
}
__device__ __forceinline__ void mma_tf32(float* d, const uint32_t* a, const uint32_t* b) {
    asm volatile(
        "mma.sync.aligned.m16n8k8.row.col.f32.tf32.tf32.f32 "
        "{%0,%1,%2,%3}, {%4,%5,%6,%7}, {%8,%9}, {%0,%1,%2,%3};"
        : "+f"(d[0]), "+f"(d[1]), "+f"(d[2]), "+f"(d[3])
        : "r"(a[0]), "r"(a[1]), "r"(a[2]), "r"(a[3]), "r"(b[0]), "r"(b[1]));
}

// ---------------------------------------------------------------------------
// Kernel 1: QKV projection via tf32 mma.sync.
// C[128x128] = X[128x128] @ W[:, head].  grid = (64 m-tiles, 8 heads, 3 z).
// 256 threads = 8 warps (2 m x 4 n), warp tile 64x32, frags m16n8k8.
// ---------------------------------------------------------------------------
__global__ __launch_bounds__(256) void qkv_mma_kernel(
    const float* __restrict__ x,
    const float* __restrict__ Wq,
    const float* __restrict__ Wk,
    const float* __restrict__ Wv)
{
    extern __shared__ float sm[];
    uint32_t* AsU = (uint32_t*)sm;                 // [128][36] tf32 bits
    uint32_t* BsU = (uint32_t*)(sm + G_AS_FLOATS); // [32][136]

    const int z  = blockIdx.z;
    const float* __restrict__ Wp = (z == 0) ? Wq : (z == 1) ? Wk : Wv;
    const int m0 = blockIdx.x * 128;
    const int h  = blockIdx.y;
    const int n0 = h * 128;

    const int tid  = threadIdx.x;
    const int warp = tid >> 5, lane = tid & 31;
    const int g = lane >> 2, tg = lane & 3;
    const int wm0 = (warp & 1) * 64;
    const int wn0 = (warp >> 1) * 32;

    float acc[4][4][4];
#pragma unroll
    for (int mi = 0; mi < 4; mi++)
#pragma unroll
        for (int ni = 0; ni < 4; ni++)
#pragma unroll
            for (int c = 0; c < 4; c++) acc[mi][ni][c] = 0.f;

    for (int kc = 0; kc < 4; kc++) {
        const int k0 = kc * 32;
        // A tile 128x32
#pragma unroll
        for (int i = 0; i < 4; i++) {
            int f = tid + i * 256;                 // 0..1023
            int row = f >> 3, s4 = f & 7;
            float4 v = *(const float4*)&x[(size_t)(m0 + row) * E_ + k0 + 4 * s4];
            AsU[row * GA_STR + 4 * s4 + 0] = f2tf32(v.x);
            AsU[row * GA_STR + 4 * s4 + 1] = f2tf32(v.y);
            AsU[row * GA_STR + 4 * s4 + 2] = f2tf32(v.z);
            AsU[row * GA_STR + 4 * s4 + 3] = f2tf32(v.w);
        }
        // B tile 32x128
#pragma unroll
        for (int i = 0; i < 4; i++) {
            int f = tid + i * 256;
            int kk = f >> 5, n4 = f & 31;
            float4 v = *(const float4*)&Wp[(size_t)(k0 + kk) * EH_ + n0 + 4 * n4];
            BsU[kk * GB_STR + 4 * n4 + 0] = f2tf32(v.x);
            BsU[kk * GB_STR + 4 * n4 + 1] = f2tf32(v.y);
            BsU[kk * GB_STR + 4 * n4 + 2] = f2tf32(v.z);
            BsU[kk * GB_STR + 4 * n4 + 3] = f2tf32(v.w);
        }
        __syncthreads();

#pragma unroll
        for (int ks = 0; ks < 4; ks++) {
            const int kb = 8 * ks;
            uint32_t a[4][4], b[4][2];
#pragma unroll
            for (int mi = 0; mi < 4; mi++) {
                int r = wm0 + 16 * mi + g;
                a[mi][0] = AsU[r * GA_STR + kb + tg];
                a[mi][1] = AsU[(r + 8) * GA_STR + kb + tg];
                a[mi][2] = AsU[r * GA_STR + kb + tg + 4];
                a[mi][3] = AsU[(r + 8) * GA_STR + kb + tg + 4];
            }
#pragma unroll
            for (int ni = 0; ni < 4; ni++) {
                int col = wn0 + 8 * ni + g;
                b[ni][0] = BsU[(kb + tg) * GB_STR + col];
                b[ni][1] = BsU[(kb + tg + 4) * GB_STR + col];
            }
#pragma unroll
            for (int mi = 0; mi < 4; mi++)
#pragma unroll
                for (int ni = 0; ni < 4; ni++)
                    mma_tf32(acc[mi][ni], a[mi], b[ni]);
        }
        __syncthreads();
    }

    const int b_ = m0 >> 11;
    const int t0 = m0 & 2047;

    if (z == 1) {
        // stage D transposed in smem, write Kg[bh][e][t] coalesced along t
        float* Ts = sm;   // [128 cols(e)][132] rows(t_local)
#pragma unroll
        for (int mi = 0; mi < 4; mi++)
#pragma unroll
            for (int ni = 0; ni < 4; ni++) {
                int rl = wm0 + 16 * mi + g;
                int cb = wn0 + 8 * ni + 2 * tg;
                Ts[cb * 132 + rl]           = acc[mi][ni][0];
                Ts[(cb + 1) * 132 + rl]     = acc[mi][ni][1];
                Ts[cb * 132 + rl + 8]       = acc[mi][ni][2];
                Ts[(cb + 1) * 132 + rl + 8] = acc[mi][ni][3];
            }
        __syncthreads();
#pragma unroll
        for (int i = 0; i < 16; i++) {
            int f = tid + i * 256;            // 0..4095
            int ln = f >> 5, c4 = f & 31;
            float4 v = *(const float4*)&Ts[ln * 132 + 4 * c4];
            size_t base = ((size_t)((b_ * H_ + h) * E_ + ln)) * T_ + t0 + 4 * c4;
            *(float4*)&Kg[base] = v;
        }
    } else {
        float* __restrict__ outp = (z == 0) ? Qg : Vg;
#pragma unroll
        for (int mi = 0; mi < 4; mi++) {
            int rl = wm0 + 16 * mi + g;
            size_t rbase = ((size_t)(b_ * H_ + h) * T_ + t0 + rl) * E_;
#pragma unroll
            for (int ni = 0; ni < 4; ni++) {
                int n = wn0 + 8 * ni + 2 * tg;
                *(float2*)&outp[rbase + n] =
                    make_float2(acc[mi][ni][0], acc[mi][ni][1]);
                *(float2*)&outp[rbase + 8 * E_ + n] =
                    make_float2(acc[mi][ni][2], acc[mi][ni][3]);
            }
        }
    }
}

// ---------------------------------------------------------------------------
// Kernel 3: output projection via tf32 mma.sync.
// out[8192x128] = Og[8192x1024] @ Wu[1024x128] + bu. grid = 64 m-tiles.
// ---------------------------------------------------------------------------
__global__ __launch_bounds__(256) void out_mma_kernel(
    const float* __restrict__ Wu,
    const float* __restrict__ bu,
    float* __restrict__ out)
{
    extern __shared__ float sm[];
    uint32_t* AsU = (uint32_t*)sm;
    uint32_t* BsU = (uint32_t*)(sm + G_AS_FLOATS);

    const int m0 = blockIdx.x * 128;
    const int tid  = threadIdx.x;
    const int warp = tid >> 5, lane = tid & 31;
    const int g = lane >> 2, tg = lane & 3;
    const int wm0 = (warp & 1) * 64;
    const int wn0 = (warp >> 1) * 32;

    float acc[4][4][4];
#pragma unroll
    for (int mi = 0; mi < 4; mi++)
#pragma unroll
        for (int ni = 0; ni < 4; ni++)
#pragma unroll
            for (int c = 0; c < 4; c++) acc[mi][ni][c] = 0.f;

    for (int kc = 0; kc < 32; kc++) {
        const int k0 = kc * 32;
#pragma unroll
        for (int i = 0; i < 4; i++) {
            int f = tid + i * 256;
            int row = f >> 3, s4 = f & 7;
            float4 v = *(const float4*)&Og[(size_t)(m0 + row) * EH_ + k0 + 4 * s4];
            AsU[row * GA_STR + 4 * s4 + 0] = f2tf32(v.x);
            AsU[row * GA_STR + 4 * s4 + 1] = f2tf32(v.y);
            AsU[row * GA_STR + 4 * s4 + 2] = f2tf32(v.z);
            AsU[row * GA_STR + 4 * s4 + 3] = f2tf32(v.w);
        }
#pragma unroll
        for (int i = 0; i < 4; i++) {
            int f = tid + i * 256;
            int kk = f >> 5, n4 = f & 31;
            float4 v = *(const float4*)&Wu[(size_t)(k0 + kk) * E_ + 4 * n4];
            BsU[kk * GB_STR + 4 * n4 + 0] = f2tf32(v.x);
            BsU[kk * GB_STR + 4 * n4 + 1] = f2tf32(v.y);
            BsU[kk * GB_STR + 4 * n4 + 2] = f2tf32(v.z);
            BsU[kk * GB_STR + 4 * n4 + 3] = f2tf32(v.w);
        }
        __syncthreads();

#pragma unroll
        for (int ks = 0; ks < 4; ks++) {
            const int kb = 8 * ks;
            uint32_t a[4][4], b[4][2];
#pragma unroll
            for (int mi = 0; mi < 4; mi++) {
                int r = wm0 + 16 * mi + g;
                a[mi][0] = AsU[r * GA_STR + kb + tg];
                a[mi][1] = AsU[(r + 8) * GA_STR + kb + tg];
                a[mi][2] = AsU[r * GA_STR + kb + tg + 4];
                a[mi][3] = AsU[(r + 8) * GA_STR + kb + tg + 4];
            }
#pragma unroll
            for (int ni = 0; ni < 4; ni++) {
                int col = wn0 + 8 * ni + g;
                b[ni][0] = BsU[(kb + tg) * GB_STR + col];
                b[ni][1] = BsU[(kb + tg + 4) * GB_STR + col];
            }
#pragma unroll
            for (int mi = 0; mi < 4; mi++)
#pragma unroll
                for (int ni = 0; ni < 4; ni++)
                    mma_tf32(acc[mi][ni], a[mi], b[ni]);
        }
        __syncthreads();
    }

#pragma unroll
    for (int mi = 0; mi < 4; mi++) {
        int m = m0 + wm0 + 16 * mi + g;
#pragma unroll
        for (int ni = 0; ni < 4; ni++) {
            int n = wn0 + 8 * ni + 2 * tg;
            float2 bias = *(const float2*)&bu[n];
            *(float2*)&out[(size_t)m * E_ + n] =
                make_float2(acc[mi][ni][0] + bias.x, acc[mi][ni][1] + bias.y);
            *(float2*)&out[(size_t)(m + 8) * E_ + n] =
                make_float2(acc[mi][ni][2] + bias.x, acc[mi][ni][3] + bias.y);
        }
    }
}

// ---------------------------------------------------------------------------
// Kernel 2: flash attention (SIMT fp32). BM=BN=64, 256 threads.
// Softmax parallelized 4 threads/row; V staged in registers by all threads.
// ---------------------------------------------------------------------------
__global__ __launch_bounds__(256, 2) void attn_kernel(const int* __restrict__ mask)
{
    extern __shared__ float sm[];
    float* Qs   = sm;                       // [64][132]
    float* Ks   = Qs + BM_ * SQ_;           // [128][68] = K^T ; V reuses as [64][132]
    float* Ss   = Ks + 128 * SK_;           // [64][65]
    float* arow = Ss + BM_ * SS_;           // [64]
    float* lrow = arow + BM_;               // [64]
    int*   needb = (int*)(lrow + BM_);

    const int bh = blockIdx.y;
    const int qt = (gridDim.x - 1) - blockIdx.x;   // heavy blocks first
    const int q0 = qt * BM_;
    const int tid = threadIdx.x;
    const int ty = tid >> 4, tx = tid & 15;
    const int r0 = 4 * ty, c0 = 4 * tx;
    const int orow = 4 * (tid >> 4);
    const int srow = tid >> 2;              // softmax row
    const int scc  = (tid & 3) * 16;        // softmax col base

    const float* __restrict__ Qp = Qg + (size_t)bh * T_ * E_;
    const float* __restrict__ Kp = Kg + (size_t)bh * E_ * T_;
    const float* __restrict__ Vp = Vg + (size_t)bh * T_ * E_;

#pragma unroll
    for (int i = 0; i < 8; i++) {
        int f = tid + i * 256;
        int row = f >> 5, c4 = f & 31;
        float4 v = *(const float4*)&Qp[(size_t)(q0 + row) * E_ + 4 * c4];
        v.x *= S2_; v.y *= S2_; v.z *= S2_; v.w *= S2_;
        *(float4*)&Qs[row * SQ_ + 4 * c4] = v;
    }

    float o[32];
#pragma unroll
    for (int j = 0; j < 32; j++) o[j] = 0.f;

    float m_i = -INFINITY;
    float l_i = 0.f;

    const int ntA = qt + 1;

    for (int kt = 0; kt < ntA; kt++) {
        const int kt0 = kt * BN_;
        __syncthreads();

#pragma unroll
        for (int i = 0; i < 8; i++) {
            int f = tid + i * 256;
            int er = f >> 4, c4 = f & 15;
            *(float4*)&Ks[er * SK_ + 4 * c4] =
                *(const float4*)&Kp[(size_t)er * T_ + kt0 + 4 * c4];
        }
        __syncthreads();

        // S = Q K^T
        {
            float acc[4][4];
#pragma unroll
            for (int i = 0; i < 4; i++)
#pragma unroll
                for (int j = 0; j < 4; j++) acc[i][j] = 0.f;

#pragma unroll 8
            for (int kc = 0; kc < 32; kc++) {
                float qa[4][4];
#pragma unroll
                for (int i = 0; i < 4; i++) {
                    float4 q = *(const float4*)&Qs[(r0 + i) * SQ_ + 4 * kc];
                    qa[i][0] = q.x; qa[i][1] = q.y; qa[i][2] = q.z; qa[i][3] = q.w;
                }
#pragma unroll
                for (int kk = 0; kk < 4; kk++) {
                    float4 kb = *(const float4*)&Ks[(4 * kc + kk) * SK_ + c0];
                    float bv[4] = {kb.x, kb.y, kb.z, kb.w};
#pragma unroll
                    for (int i = 0; i < 4; i++)
#pragma unroll
                        for (int j = 0; j < 4; j++)
                            acc[i][j] += qa[i][kk] * bv[j];
                }
            }
#pragma unroll
            for (int i = 0; i < 4; i++) {
                int q = q0 + r0 + i;
                int4 mrow = *(const int4*)&mask[(size_t)q * T_ + kt0 + c0];
                int mv[4] = {mrow.x, mrow.y, mrow.z, mrow.w};
#pragma unroll
                for (int j = 0; j < 4; j++) {
                    int k = kt0 + c0 + j;
                    float s = acc[i][j];
                    if (k > q) s = -INFINITY;
                    if (mv[j] == 0) s = -1e9f;
                    Ss[(r0 + i) * SS_ + c0 + j] = s;
                }
            }
        }
        __syncthreads();

        // V stage (all threads, regs) + parallel softmax (4 threads/row)
        float4 vst[8];
#pragma unroll
        for (int i = 0; i < 8; i++) {
            int f = tid + i * 256;
            int row = f >> 5, c4 = f & 31;
            vst[i] = *(const float4*)&Vp[(size_t)(kt0 + row) * E_ + 4 * c4];
        }
        {
            float sv[16];
#pragma unroll
            for (int c = 0; c < 16; c++) sv[c] = Ss[srow * SS_ + scc + c];
            float mt = sv[0];
#pragma unroll
            for (int c = 1; c < 16; c++) mt = fmaxf(mt, sv[c]);
            mt = fmaxf(mt, __shfl_xor_sync(0xffffffffu, mt, 1));
            mt = fmaxf(mt, __shfl_xor_sync(0xffffffffu, mt, 2));
            float mn = fmaxf(m_i, mt);
            float alpha = __expf(m_i - mn);
            float lsum = 0.f;
#pragma unroll
            for (int c = 0; c < 16; c++) {
                float p = __expf(sv[c] - mn);
                Ss[srow * SS_ + scc + c] = p;
                lsum += p;
            }
            lsum += __shfl_xor_sync(0xffffffffu, lsum, 1);
            lsum += __shfl_xor_sync(0xffffffffu, lsum, 2);
            l_i = l_i * alpha + lsum;
            m_i = mn;
            if ((tid & 3) == 0) arow[srow] = alpha;
        }
#pragma unroll
        for (int i = 0; i < 8; i++) {
            int f = tid + i * 256;
            int row = f >> 5, c4 = f & 31;
            *(float4*)&Ks[row * SQ_ + 4 * c4] = vst[i];
        }
        __syncthreads();

        // O = O*alpha + P @ V
        {
            float al[4];
#pragma unroll
            for (int i = 0; i < 4; i++) al[i] = arow[orow + i];
#pragma unroll
            for (int i = 0; i < 4; i++)
#pragma unroll
                for (int j = 0; j < 8; j++) o[i * 8 + j] *= al[i];

#pragma unroll 4
            for (int kk = 0; kk < 64; kk++) {
                float p[4];
#pragma unroll
                for (int i = 0; i < 4; i++) p[i] = Ss[(orow + i) * SS_ + kk];
                float4 v0 = *(const float4*)&Ks[kk * SQ_ + 4 * tx];
                float4 v1 = *(const float4*)&Ks[kk * SQ_ + 64 + 4 * tx];
                float vv[8] = {v0.x, v0.y, v0.z, v0.w, v1.x, v1.y, v1.z, v1.w};
#pragma unroll
                for (int i = 0; i < 4; i++)
#pragma unroll
                    for (int j = 0; j < 8; j++) o[i * 8 + j] += p[i] * vv[j];
            }
        }
    }

    // Phase B: rows whose entire causal range was masked attend to future
    // mask==0 positions (reference semantics: -1e9 beats -inf). Rare.
    __syncthreads();
    if (tid == 0) *needb = 0;
    __syncthreads();
    if (m_i < -1e8f) *needb = 1;
    __syncthreads();

    if (*needb) {
        for (int kt = ntA; kt < T_ / BN_; kt++) {
            const int kt0 = kt * BN_;
            __syncthreads();
#pragma unroll
            for (int i = 0; i < 8; i++) {
                int f = tid + i * 256;
                int row = f >> 5, c4 = f & 31;
                *(float4*)&Ks[row * SQ_ + 4 * c4] =
                    *(const float4*)&Vp[(size_t)(kt0 + row) * E_ + 4 * c4];
            }
#pragma unroll
            for (int i = 0; i < 4; i++) {
                int q = q0 + r0 + i;
                int4 mrow = *(const int4*)&mask[(size_t)q * T_ + kt0 + c0];
                int mv[4] = {mrow.x, mrow.y, mrow.z, mrow.w};
#pragma unroll
                for (int j = 0; j < 4; j++)
                    Ss[(r0 + i) * SS_ + c0 + j] = (mv[j] == 0) ? -1e9f : -INFINITY;
            }
            __syncthreads();
            {
                float sv[16];
#pragma unroll
                for (int c = 0; c < 16; c++) sv[c] = Ss[srow * SS_ + scc + c];
                float mt = sv[0];
#pragma unroll
                for (int c = 1; c < 16; c++) mt = fmaxf(mt, sv[c]);
                mt = fmaxf(mt, __shfl_xor_sync(0xffffffffu, mt, 1));
                mt = fmaxf(mt, __shfl_xor_sync(0xffffffffu, mt, 2));
                float mn = fmaxf(m_i, mt);
                float alpha = __expf(m_i - mn);
                float lsum = 0.f;
#pragma unroll
                for (int c = 0; c < 16; c++) {
                    float p = __expf(sv[c] - mn);
                    Ss[srow * SS_ + scc + c] = p;
                    lsum += p;
                }
                lsum += __shfl_xor_sync(0xffffffffu, lsum, 1);
                lsum += __shfl_xor_sync(0xffffffffu, lsum, 2);
                l_i = l_i * alpha + lsum;
                m_i = mn;
                if ((tid & 3) == 0) arow[srow] = alpha;
            }
            __syncthreads();
            {
                float al[4];
#pragma unroll
                for (int i = 0; i < 4; i++) al[i] = arow[orow + i];
#pragma unroll
                for (int i = 0; i < 4; i++)
#pragma unroll
                    for (int j = 0; j < 8; j++) o[i * 8 + j] *= al[i];
#pragma unroll 4
                for (int kk = 0; kk < 64; kk++) {
                    float p[4];
#pragma unroll
                    for (int i = 0; i < 4; i++) p[i] = Ss[(orow + i) * SS_ + kk];
                    float4 v0 = *(const float4*)&Ks[kk * SQ_ + 4 * tx];
                    float4 v1 = *(const float4*)&Ks[kk * SQ_ + 64 + 4 * tx];
                    float vv[8] = {v0.x, v0.y, v0.z, v0.w, v1.x, v1.y, v1.z, v1.w};
#pragma unroll
                    for (int i = 0; i < 4; i++)
#pragma unroll
                        for (int j = 0; j < 8; j++) o[i * 8 + j] += p[i] * vv[j];
                }
            }
        }
    }

    __syncthreads();
    if ((tid & 3) == 0) lrow[srow] = l_i;
    __syncthreads();

    const int b = bh >> 3, h = bh & 7;
#pragma unroll
    for (int i = 0; i < 4; i++) {
        float inv = 1.0f / lrow[orow + i];
        size_t base = ((size_t)(b * T_ + q0 + orow + i)) * EH_ + h * E_;
        float4 w0 = make_float4(o[i * 8 + 0] * inv, o[i * 8 + 1] * inv,
                                o[i * 8 + 2] * inv, o[i * 8 + 3] * inv);
        float4 w1 = make_float4(o[i * 8 + 4] * inv, o[i * 8 + 5] * inv,
                                o[i * 8 + 6] * inv, o[i * 8 + 7] * inv);
        *(float4*)&Og[base + 4 * tx] = w0;
        *(float4*)&Og[base + 64 + 4 * tx] = w1;
    }
}

// ---------------------------------------------------------------------------
extern "C" void kernel_launch(void* const* d_in, const int* in_sizes, int n_in,
                              void* d_out, int out_size)
{
    const float* x   = (const float*)d_in[0];
    const int*  mask = (const int*)  d_in[1];
    const float* Wq  = (const float*)d_in[2];
    const float* Wk  = (const float*)d_in[3];
    const float* Wv  = (const float*)d_in[4];
    const float* Wu  = (const float*)d_in[5];
    const float* bu  = (const float*)d_in[6];
    float* out = (float*)d_out;

    cudaFuncSetAttribute(attn_kernel,
                         cudaFuncAttributeMaxDynamicSharedMemorySize, SMEM_ATTN);
    cudaFuncSetAttribute(qkv_mma_kernel,
                         cudaFuncAttributeMaxDynamicSharedMemorySize, SMEM_QKV);
    cudaFuncSetAttribute(out_mma_kernel,
                         cudaFuncAttributeMaxDynamicSharedMemorySize, SMEM_OUT);

    qkv_mma_kernel<<<dim3(M_ / 128, H_, 3), 256, SMEM_QKV>>>(x, Wq, Wk, Wv);
    attn_kernel<<<dim3(T_ / BM_, BH_), 256, SMEM_ATTN>>>(mask);
    out_mma_kernel<<<dim3(M_ / 128, 1, 1), 256, SMEM_OUT>>>(Wu, bu, out);
}

// round 7
// speedup vs baseline: 5.2504x; 1.8541x over previous
#include <cuda_runtime.h>
#include <math.h>
#include <stdint.h>

#define B_  4
#define T_  2048
#define E_  128
#define H_  8
#define BH_ 32
#define M_  8192      // B*T
#define EH_ 1024      // E*H

// total softmax scale: e^-0.5 (folded into Q)
#define S2_ 0.08838834764831845f

// Projection GEMM smem (floats): As[128][36], Bs[32][136]
#define GA_STR 36
#define GB_STR 136
#define G_AS_FLOATS (128 * GA_STR)
#define G_BS_FLOATS (32 * GB_STR)
#define SMEM_GEMM ((G_AS_FLOATS + G_BS_FLOATS) * 4)   // 35840 B

// Attention smem (u32 tf32 bits)
#define AQ_STR 132
#define AK_STR 132
#define AV_STR 132
#define AP_STR 68
#define ATT_Q_U32 (128 * AQ_STR)
#define ATT_K_U32 (64 * AK_STR)
#define ATT_V_U32 (64 * AV_STR)
#define ATT_P_U32 (128 * AP_STR)
#define SMEM_ATTN ((ATT_Q_U32 + ATT_K_U32 + ATT_V_U32 + ATT_P_U32) * 4 + 16) // ~170KB

// Scratch (device globals: allowed; runtime alloc is not)
__device__ float Qg[(size_t)BH_ * T_ * E_];   // [bh][t][e]
__device__ float Kg[(size_t)BH_ * T_ * E_];   // [bh][t][e] (natural)
__device__ float Vg[(size_t)BH_ * T_ * E_];   // [bh][t][e]
__device__ float Og[(size_t)M_ * EH_];        // [b*t][h*e]

// ---------------------------------------------------------------------------
// mma.sync tf32 helpers (sm_80+, no arch-feature suffix needed)
// ---------------------------------------------------------------------------
__device__ __forceinline__ uint32_t f2tf32(float f) {
    uint32_t r;
    asm("cvt.rna.tf32.f32 %0, %1;" : "=r"(r) : "f"(f));
    return r;
}
__device__ __forceinline__ void mma_tf32(float* d, const uint32_t* a, const uint32_t* b) {
    asm volatile(
        "mma.sync.aligned.m16n8k8.row.col.f32.tf32.tf32.f32 "
        "{%0,%1,%2,%3}, {%4,%5,%6,%7}, {%8,%9}, {%0,%1,%2,%3};"
        : "+f"(d[0]), "+f"(d[1]), "+f"(d[2]), "+f"(d[3])
        : "r"(a[0]), "r"(a[1]), "r"(a[2]), "r"(a[3]), "r"(b[0]), "r"(b[1]));
}

// ---------------------------------------------------------------------------
// Kernel 1: QKV projection via tf32 mma.sync. All outputs natural [bh][t][e].
// grid = (64 m-tiles, 8 heads, 3 z). 256 threads, warp tile 64x32.
// ---------------------------------------------------------------------------
__global__ __launch_bounds__(256) void qkv_mma_kernel(
    const float* __restrict__ x,
    const float* __restrict__ Wq,
    const float* __restrict__ Wk,
    const float* __restrict__ Wv)
{
    extern __shared__ float sm[];
    uint32_t* AsU = (uint32_t*)sm;
    uint32_t* BsU = (uint32_t*)(sm + G_AS_FLOATS);

    const int z  = blockIdx.z;
    const float* __restrict__ Wp = (z == 0) ? Wq : (z == 1) ? Wk : Wv;
    float* __restrict__ outp     = (z == 0) ? Qg : (z == 1) ? Kg : Vg;
    const int m0 = blockIdx.x * 128;
    const int h  = blockIdx.y;
    const int n0 = h * 128;

    const int tid  = threadIdx.x;
    const int warp = tid >> 5, lane = tid & 31;
    const int g = lane >> 2, tg = lane & 3;
    const int wm0 = (warp & 1) * 64;
    const int wn0 = (warp >> 1) * 32;

    float acc[4][4][4];
#pragma unroll
    for (int mi = 0; mi < 4; mi++)
#pragma unroll
        for (int ni = 0; ni < 4; ni++)
#pragma unroll
            for (int c = 0; c < 4; c++) acc[mi][ni][c] = 0.f;

    for (int kc = 0; kc < 4; kc++) {
        const int k0 = kc * 32;
#pragma unroll
        for (int i = 0; i < 4; i++) {
            int f = tid + i * 256;
            int row = f >> 3, s4 = f & 7;
            float4 v = *(const float4*)&x[(size_t)(m0 + row) * E_ + k0 + 4 * s4];
            AsU[row * GA_STR + 4 * s4 + 0] = f2tf32(v.x);
            AsU[row * GA_STR + 4 * s4 + 1] = f2tf32(v.y);
            AsU[row * GA_STR + 4 * s4 + 2] = f2tf32(v.z);
            AsU[row * GA_STR + 4 * s4 + 3] = f2tf32(v.w);
        }
#pragma unroll
        for (int i = 0; i < 4; i++) {
            int f = tid + i * 256;
            int kk = f >> 5, n4 = f & 31;
            float4 v = *(const float4*)&Wp[(size_t)(k0 + kk) * EH_ + n0 + 4 * n4];
            BsU[kk * GB_STR + 4 * n4 + 0] = f2tf32(v.x);
            BsU[kk * GB_STR + 4 * n4 + 1] = f2tf32(v.y);
            BsU[kk * GB_STR + 4 * n4 + 2] = f2tf32(v.z);
            BsU[kk * GB_STR + 4 * n4 + 3] = f2tf32(v.w);
        }
        __syncthreads();

#pragma unroll
        for (int ks = 0; ks < 4; ks++) {
            const int kb = 8 * ks;
            uint32_t a[4][4], b[4][2];
#pragma unroll
            for (int mi = 0; mi < 4; mi++) {
                int r = wm0 + 16 * mi + g;
                a[mi][0] = AsU[r * GA_STR + kb + tg];
                a[mi][1] = AsU[(r + 8) * GA_STR + kb + tg];
                a[mi][2] = AsU[r * GA_STR + kb + tg + 4];
                a[mi][3] = AsU[(r + 8) * GA_STR + kb + tg + 4];
            }
#pragma unroll
            for (int ni = 0; ni < 4; ni++) {
                int col = wn0 + 8 * ni + g;
                b[ni][0] = BsU[(kb + tg) * GB_STR + col];
                b[ni][1] = BsU[(kb + tg + 4) * GB_STR + col];
            }
#pragma unroll
            for (int mi = 0; mi < 4; mi++)
#pragma unroll
                for (int ni = 0; ni < 4; ni++)
                    mma_tf32(acc[mi][ni], a[mi], b[ni]);
        }
        __syncthreads();
    }

    const int b_ = m0 >> 11;
    const int t0 = m0 & 2047;
#pragma unroll
    for (int mi = 0; mi < 4; mi++) {
        int rl = wm0 + 16 * mi + g;
        size_t rbase = ((size_t)(b_ * H_ + h) * T_ + t0 + rl) * E_;
#pragma unroll
        for (int ni = 0; ni < 4; ni++) {
            int n = wn0 + 8 * ni + 2 * tg;
            *(float2*)&outp[rbase + n] =
                make_float2(acc[mi][ni][0], acc[mi][ni][1]);
            *(float2*)&outp[rbase + 8 * E_ + n] =
                make_float2(acc[mi][ni][2], acc[mi][ni][3]);
        }
    }
}

// ---------------------------------------------------------------------------
// Kernel 3: output projection via tf32 mma.sync. grid = 64 m-tiles.
// ---------------------------------------------------------------------------
__global__ __launch_bounds__(256) void out_mma_kernel(
    const float* __restrict__ Wu,
    const float* __restrict__ bu,
    float* __restrict__ out)
{
    extern __shared__ float sm[];
    uint32_t* AsU = (uint32_t*)sm;
    uint32_t* BsU = (uint32_t*)(sm + G_AS_FLOATS);

    const int m0 = blockIdx.x * 128;
    const int tid  = threadIdx.x;
    const int warp = tid >> 5, lane = tid & 31;
    const int g = lane >> 2, tg = lane & 3;
    const int wm0 = (warp & 1) * 64;
    const int wn0 = (warp >> 1) * 32;

    float acc[4][4][4];
#pragma unroll
    for (int mi = 0; mi < 4; mi++)
#pragma unroll
        for (int ni = 0; ni < 4; ni++)
#pragma unroll
            for (int c = 0; c < 4; c++) acc[mi][ni][c] = 0.f;

    for (int kc = 0; kc < 32; kc++) {
        const int k0 = kc * 32;
#pragma unroll
        for (int i = 0; i < 4; i++) {
            int f = tid + i * 256;
            int row = f >> 3, s4 = f & 7;
            float4 v = *(const float4*)&Og[(size_t)(m0 + row) * EH_ + k0 + 4 * s4];
            AsU[row * GA_STR + 4 * s4 + 0] = f2tf32(v.x);
            AsU[row * GA_STR + 4 * s4 + 1] = f2tf32(v.y);
            AsU[row * GA_STR + 4 * s4 + 2] = f2tf32(v.z);
            AsU[row * GA_STR + 4 * s4 + 3] = f2tf32(v.w);
        }
#pragma unroll
        for (int i = 0; i < 4; i++) {
            int f = tid + i * 256;
            int kk = f >> 5, n4 = f & 31;
            float4 v = *(const float4*)&Wu[(size_t)(k0 + kk) * E_ + 4 * n4];
            BsU[kk * GB_STR + 4 * n4 + 0] = f2tf32(v.x);
            BsU[kk * GB_STR + 4 * n4 + 1] = f2tf32(v.y);
            BsU[kk * GB_STR + 4 * n4 + 2] = f2tf32(v.z);
            BsU[kk * GB_STR + 4 * n4 + 3] = f2tf32(v.w);
        }
        __syncthreads();

#pragma unroll
        for (int ks = 0; ks < 4; ks++) {
            const int kb = 8 * ks;
            uint32_t a[4][4], b[4][2];
#pragma unroll
            for (int mi = 0; mi < 4; mi++) {
                int r = wm0 + 16 * mi + g;
                a[mi][0] = AsU[r * GA_STR + kb + tg];
                a[mi][1] = AsU[(r + 8) * GA_STR + kb + tg];
                a[mi][2] = AsU[r * GA_STR + kb + tg + 4];
                a[mi][3] = AsU[(r + 8) * GA_STR + kb + tg + 4];
            }
#pragma unroll
            for (int ni = 0; ni < 4; ni++) {
                int col = wn0 + 8 * ni + g;
                b[ni][0] = BsU[(kb + tg) * GB_STR + col];
                b[ni][1] = BsU[(kb + tg + 4) * GB_STR + col];
            }
#pragma unroll
            for (int mi = 0; mi < 4; mi++)
#pragma unroll
                for (int ni = 0; ni < 4; ni++)
                    mma_tf32(acc[mi][ni], a[mi], b[ni]);
        }
        __syncthreads();
    }

#pragma unroll
    for (int mi = 0; mi < 4; mi++) {
        int m = m0 + wm0 + 16 * mi + g;
#pragma unroll
        for (int ni = 0; ni < 4; ni++) {
            int n = wn0 + 8 * ni + 2 * tg;
            float2 bias = *(const float2*)&bu[n];
            *(float2*)&out[(size_t)m * E_ + n] =
                make_float2(acc[mi][ni][0] + bias.x, acc[mi][ni][1] + bias.y);
            *(float2*)&out[(size_t)(m + 8) * E_ + n] =
                make_float2(acc[mi][ni][2] + bias.x, acc[mi][ni][3] + bias.y);
        }
    }
}

// ---------------------------------------------------------------------------
// Attention: register online-softmax + P staging + PV mma.
// sacc[8][4] holds masked scores; state (m,l) per thread for rows r1, r1+8.
// ---------------------------------------------------------------------------
__device__ __forceinline__ void attn_softmax_pv(
    float sacc[8][4], float& m1, float& m2, float& l1, float& l2,
    float o[16][4], uint32_t* Ps, const uint32_t* Vs, int r1, int g, int tg)
{
    float mt1 = -INFINITY, mt2 = -INFINITY;
#pragma unroll
    for (int ni = 0; ni < 8; ni++) {
        mt1 = fmaxf(mt1, fmaxf(sacc[ni][0], sacc[ni][1]));
        mt2 = fmaxf(mt2, fmaxf(sacc[ni][2], sacc[ni][3]));
    }
    mt1 = fmaxf(mt1, __shfl_xor_sync(0xffffffffu, mt1, 1));
    mt1 = fmaxf(mt1, __shfl_xor_sync(0xffffffffu, mt1, 2));
    mt2 = fmaxf(mt2, __shfl_xor_sync(0xffffffffu, mt2, 1));
    mt2 = fmaxf(mt2, __shfl_xor_sync(0xffffffffu, mt2, 2));
    float mn1 = fmaxf(m1, mt1), mn2 = fmaxf(m2, mt2);
    float al1 = (m1 == mn1) ? 1.f : __expf(m1 - mn1);
    float al2 = (m2 == mn2) ? 1.f : __expf(m2 - mn2);
    float me1 = (mn1 == -INFINITY) ? 0.f : mn1;
    float me2 = (mn2 == -INFINITY) ? 0.f : mn2;
    float ls1 = 0.f, ls2 = 0.f;
#pragma unroll
    for (int ni = 0; ni < 8; ni++) {
        float p0 = __expf(sacc[ni][0] - me1);
        float p1 = __expf(sacc[ni][1] - me1);
        float p2 = __expf(sacc[ni][2] - me2);
        float p3 = __expf(sacc[ni][3] - me2);
        ls1 += p0 + p1; ls2 += p2 + p3;
        uint32_t* pb = Ps + r1 * AP_STR + 8 * ni + 2 * tg;
        pb[0] = f2tf32(p0); pb[1] = f2tf32(p1);
        pb[8 * AP_STR] = f2tf32(p2); pb[8 * AP_STR + 1] = f2tf32(p3);
    }
    ls1 += __shfl_xor_sync(0xffffffffu, ls1, 1);
    ls1 += __shfl_xor_sync(0xffffffffu, ls1, 2);
    ls2 += __shfl_xor_sync(0xffffffffu, ls2, 1);
    ls2 += __shfl_xor_sync(0xffffffffu, ls2, 2);
    l1 = l1 * al1 + ls1; m1 = mn1;
    l2 = l2 * al2 + ls2; m2 = mn2;
#pragma unroll
    for (int ni = 0; ni < 16; ni++) {
        o[ni][0] *= al1; o[ni][1] *= al1;
        o[ni][2] *= al2; o[ni][3] *= al2;
    }
    __syncwarp();
#pragma unroll
    for (int kp = 0; kp < 8; kp++) {
        uint32_t a[4];
        const uint32_t* pb = Ps + r1 * AP_STR + 8 * kp;
        a[0] = pb[tg]; a[1] = pb[8 * AP_STR + tg];
        a[2] = pb[tg + 4]; a[3] = pb[8 * AP_STR + tg + 4];
#pragma unroll
        for (int ni = 0; ni < 16; ni++) {
            const uint32_t* vb = Vs + (8 * kp + tg) * AV_STR + 8 * ni + g;
            uint32_t b[2] = { vb[0], vb[4 * AV_STR] };
            mma_tf32(o[ni], a, b);
        }
    }
    __syncwarp();   // all lanes done reading Ps before next tile overwrites
}

__global__ __launch_bounds__(256, 1) void attn_kernel(const int* __restrict__ mask)
{
    extern __shared__ uint32_t smu[];
    uint32_t* Qs = smu;
    uint32_t* Ks = Qs + ATT_Q_U32;
    uint32_t* Vs = Ks + ATT_K_U32;
    uint32_t* Ps = Vs + ATT_V_U32;
    int* needb = (int*)(Ps + ATT_P_U32);

    const int bh = blockIdx.y;
    const int qt = (gridDim.x - 1) - blockIdx.x;   // heavy blocks first
    const int q0 = qt * 128;
    const int tid = threadIdx.x;
    const int w = tid >> 5, lane = tid & 31;
    const int g = lane >> 2, tg = lane & 3;
    const int r1 = 16 * w + g;                     // local rows r1, r1+8
    const int gq1 = q0 + r1, gq2 = gq1 + 8;

    const float* __restrict__ Qp = Qg + (size_t)bh * T_ * E_;
    const float* __restrict__ Kp = Kg + (size_t)bh * T_ * E_;
    const float* __restrict__ Vp = Vg + (size_t)bh * T_ * E_;

    // Q tile 128x128 -> tf32 bits, pre-scaled by e^-0.5
#pragma unroll
    for (int i = 0; i < 16; i++) {
        int f = tid + i * 256;
        int row = f >> 5, c4 = f & 31;
        float4 v = *(const float4*)&Qp[(size_t)(q0 + row) * E_ + 4 * c4];
        uint32_t* d = Qs + row * AQ_STR + 4 * c4;
        d[0] = f2tf32(v.x * S2_); d[1] = f2tf32(v.y * S2_);
        d[2] = f2tf32(v.z * S2_); d[3] = f2tf32(v.w * S2_);
    }

    float o[16][4];
#pragma unroll
    for (int ni = 0; ni < 16; ni++)
#pragma unroll
        for (int c = 0; c < 4; c++) o[ni][c] = 0.f;

    float m1 = -INFINITY, m2 = -INFINITY, l1 = 0.f, l2 = 0.f;
    const int ntA = 2 * qt + 2;

    for (int kt = 0; kt < ntA; kt++) {
        const int kt0 = kt * 64;
        __syncthreads();
        // load K and V tiles (64 x 128 each) -> tf32 bits
#pragma unroll
        for (int i = 0; i < 8; i++) {
            int f = tid + i * 256;
            int row = f >> 5, c4 = f & 31;
            float4 kv = *(const float4*)&Kp[(size_t)(kt0 + row) * E_ + 4 * c4];
            uint32_t* d = Ks + row * AK_STR + 4 * c4;
            d[0] = f2tf32(kv.x); d[1] = f2tf32(kv.y);
            d[2] = f2tf32(kv.z); d[3] = f2tf32(kv.w);
            float4 vv = *(const float4*)&Vp[(size_t)(kt0 + row) * E_ + 4 * c4];
            uint32_t* e = Vs + row * AV_STR + 4 * c4;
            e[0] = f2tf32(vv.x); e[1] = f2tf32(vv.y);
            e[2] = f2tf32(vv.z); e[3] = f2tf32(vv.w);
        }
        __syncthreads();

        if (q0 + 16 * w + 15 >= kt0) {
            // active warp: full S = Q K^T
            float sacc[8][4];
#pragma unroll
            for (int ni = 0; ni < 8; ni++)
#pragma unroll
                for (int c = 0; c < 4; c++) sacc[ni][c] = 0.f;

#pragma unroll
            for (int ks = 0; ks < 16; ks++) {
                uint32_t a[4];
                const uint32_t* qb = Qs + r1 * AQ_STR + 8 * ks;
                a[0] = qb[tg]; a[1] = qb[8 * AQ_STR + tg];
                a[2] = qb[tg + 4]; a[3] = qb[8 * AQ_STR + tg + 4];
#pragma unroll
                for (int ni = 0; ni < 8; ni++) {
                    const uint32_t* kb = Ks + (8 * ni + g) * AK_STR + 8 * ks;
                    uint32_t b[2] = { kb[tg], kb[tg + 4] };
                    mma_tf32(sacc[ni], a, b);
                }
            }
            // causal + external mask (mask==0 -> -1e9 overrides causal -inf)
#pragma unroll
            for (int ni = 0; ni < 8; ni++) {
                int k1 = kt0 + 8 * ni + 2 * tg;
                int2 ma = *(const int2*)&mask[(size_t)gq1 * T_ + k1];
                int2 mb = *(const int2*)&mask[(size_t)gq2 * T_ + k1];
                if (k1 > gq1)     sacc[ni][0] = -INFINITY;
                if (k1 + 1 > gq1) sacc[ni][1] = -INFINITY;
                if (k1 > gq2)     sacc[ni][2] = -INFINITY;
                if (k1 + 1 > gq2) sacc[ni][3] = -INFINITY;
                if (ma.x == 0) sacc[ni][0] = -1e9f;
                if (ma.y == 0) sacc[ni][1] = -1e9f;
                if (mb.x == 0) sacc[ni][2] = -1e9f;
                if (mb.y == 0) sacc[ni][3] = -1e9f;
            }
            attn_softmax_pv(sacc, m1, m2, l1, l2, o, Ps, Vs, r1, g, tg);
        } else {
            // fully-future tile for this warp: matters only for dead rows
            unsigned anyd = __any_sync(0xffffffffu, (m1 < -1e8f) || (m2 < -1e8f));
            if (anyd) {
                float sacc[8][4];
#pragma unroll
                for (int ni = 0; ni < 8; ni++) {
                    int k1 = kt0 + 8 * ni + 2 * tg;
                    int2 ma = *(const int2*)&mask[(size_t)gq1 * T_ + k1];
                    int2 mb = *(const int2*)&mask[(size_t)gq2 * T_ + k1];
                    sacc[ni][0] = ma.x ? -INFINITY : -1e9f;
                    sacc[ni][1] = ma.y ? -INFINITY : -1e9f;
                    sacc[ni][2] = mb.x ? -INFINITY : -1e9f;
                    sacc[ni][3] = mb.y ? -INFINITY : -1e9f;
                }
                attn_softmax_pv(sacc, m1, m2, l1, l2, o, Ps, Vs, r1, g, tg);
            }
        }
    }

    // Phase B: fully-masked rows attend to future mask==0 positions
    __syncthreads();
    if (tid == 0) *needb = 0;
    __syncthreads();
    if ((m1 < -1e8f) || (m2 < -1e8f)) *needb = 1;
    __syncthreads();
    if (*needb) {
        for (int kt = ntA; kt < T_ / 64; kt++) {
            const int kt0 = kt * 64;
            __syncthreads();
#pragma unroll
            for (int i = 0; i < 8; i++) {
                int f = tid + i * 256;
                int row = f >> 5, c4 = f & 31;
                float4 vv = *(const float4*)&Vp[(size_t)(kt0 + row) * E_ + 4 * c4];
                uint32_t* e = Vs + row * AV_STR + 4 * c4;
                e[0] = f2tf32(vv.x); e[1] = f2tf32(vv.y);
                e[2] = f2tf32(vv.z); e[3] = f2tf32(vv.w);
            }
            __syncthreads();
            unsigned anyd = __any_sync(0xffffffffu, (m1 < -1e8f) || (m2 < -1e8f));
            if (anyd) {
                float sacc[8][4];
#pragma unroll
                for (int ni = 0; ni < 8; ni++) {
                    int k1 = kt0 + 8 * ni + 2 * tg;
                    int2 ma = *(const int2*)&mask[(size_t)gq1 * T_ + k1];
                    int2 mb = *(const int2*)&mask[(size_t)gq2 * T_ + k1];
                    sacc[ni][0] = ma.x ? -INFINITY : -1e9f;
                    sacc[ni][1] = ma.y ? -INFINITY : -1e9f;
                    sacc[ni][2] = mb.x ? -INFINITY : -1e9f;
                    sacc[ni][3] = mb.y ? -INFINITY : -1e9f;
                }
                attn_softmax_pv(sacc, m1, m2, l1, l2, o, Ps, Vs, r1, g, tg);
            }
        }
    }

    // epilogue: normalize and write Og[b*t][h*e]
    float inv1 = 1.f / l1, inv2 = 1.f / l2;
    const int b = bh >> 3, h = bh & 7;
    size_t base1 = ((size_t)(b * T_ + gq1)) * EH_ + h * E_;
    size_t base2 = base1 + (size_t)8 * EH_;
#pragma unroll
    for (int ni = 0; ni < 16; ni++) {
        int col = 8 * ni + 2 * tg;
        *(float2*)&Og[base1 + col] = make_float2(o[ni][0] * inv1, o[ni][1] * inv1);
        *(float2*)&Og[base2 + col] = make_float2(o[ni][2] * inv2, o[ni][3] * inv2);
    }
}

// ---------------------------------------------------------------------------
extern "C" void kernel_launch(void* const* d_in, const int* in_sizes, int n_in,
                              void* d_out, int out_size)
{
    const float* x   = (const float*)d_in[0];
    const int*  mask = (const int*)  d_in[1];
    const float* Wq  = (const float*)d_in[2];
    const float* Wk  = (const float*)d_in[3];
    const float* Wv  = (const float*)d_in[4];
    const float* Wu  = (const float*)d_in[5];
    const float* bu  = (const float*)d_in[6];
    float* out = (float*)d_out;

    cudaFuncSetAttribute(attn_kernel,
                         cudaFuncAttributeMaxDynamicSharedMemorySize, SMEM_ATTN);
    cudaFuncSetAttribute(qkv_mma_kernel,
                         cudaFuncAttributeMaxDynamicSharedMemorySize, SMEM_GEMM);
    cudaFuncSetAttribute(out_mma_kernel,
                         cudaFuncAttributeMaxDynamicSharedMemorySize, SMEM_GEMM);

    qkv_mma_kernel<<<dim3(M_ / 128, H_, 3), 256, SMEM_GEMM>>>(x, Wq, Wk, Wv);
    attn_kernel<<<dim3(T_ / 128, BH_), 256, SMEM_ATTN>>>(mask);
    out_mma_kernel<<<dim3(M_ / 128, 1, 1), 256, SMEM_GEMM>>>(Wu, bu, out);
}

// round 8
// speedup vs baseline: 5.6370x; 1.0736x over previous
#include <cuda_runtime.h>
#include <math.h>
#include <stdint.h>

#define B_  4
#define T_  2048
#define E_  128
#define H_  8
#define BH_ 32
#define M_  8192      // B*T
#define EH_ 1024      // E*H

// total softmax scale: e^-0.5 (folded into Q)
#define S2_ 0.08838834764831845f

// Projection GEMM smem (floats)
#define GA_STR 36
#define GB_STR 136
#define G_AS_FLOATS (128 * GA_STR)
#define G_BS_FLOATS (32 * GB_STR)
#define SMEM_GEMM ((G_AS_FLOATS + G_BS_FLOATS) * 4)     // qkv kernel

#define G_AS2_FLOATS (64 * GA_STR)
#define SMEM_OUT ((G_AS2_FLOATS + G_BS_FLOATS) * 4)     // out kernel (M-tile 64)

// Attention smem: KV stages (raw fp32 bits) + P (tf32 bits) + flag
#define AK_STR 132
#define AV_STR 132
#define AP_STR 68
#define ST_U32 (64 * AK_STR)                 // one K or V stage
#define SMEM_ATTN ((4 * ST_U32 + 128 * AP_STR + 4) * 4)  // ~170KB

// Scratch (device globals: allowed; runtime alloc is not)
__device__ float Qg[(size_t)BH_ * T_ * E_];   // [bh][t][e]
__device__ float Kg[(size_t)BH_ * T_ * E_];   // [bh][t][e]
__device__ float Vg[(size_t)BH_ * T_ * E_];   // [bh][t][e]
__device__ float Og[(size_t)M_ * EH_];        // [b*t][h*e]

// ---------------------------------------------------------------------------
// helpers (sm_80+ only; toolchain compiles at compute_100 non-a)
// ---------------------------------------------------------------------------
__device__ __forceinline__ uint32_t f2tf32(float f) {
    uint32_t r;
    asm("cvt.rna.tf32.f32 %0, %1;" : "=r"(r) : "f"(f));
    return r;
}
__device__ __forceinline__ void mma_tf32(float* d, const uint32_t* a, const uint32_t* b) {
    asm volatile(
        "mma.sync.aligned.m16n8k8.row.col.f32.tf32.tf32.f32 "
        "{%0,%1,%2,%3}, {%4,%5,%6,%7}, {%8,%9}, {%0,%1,%2,%3};"
        : "+f"(d[0]), "+f"(d[1]), "+f"(d[2]), "+f"(d[3])
        : "r"(a[0]), "r"(a[1]), "r"(a[2]), "r"(a[3]), "r"(b[0]), "r"(b[1]));
}
__device__ __forceinline__ uint32_t smem_u32addr(const void* p) {
    uint32_t a;
    asm("{ .reg .u64 t; cvta.to.shared.u64 t, %1; cvt.u32.u64 %0, t; }"
        : "=r"(a) : "l"(p));
    return a;
}
__device__ __forceinline__ void cpa16(uint32_t s, const void* g) {
    asm volatile("cp.async.cg.shared.global [%0], [%1], 16;" :: "r"(s), "l"(g));
}
#define CPA_COMMIT() asm volatile("cp.async.commit_group;" ::: "memory")
#define CPA_WAIT1()  asm volatile("cp.async.wait_group 1;" ::: "memory")
#define CPA_WAIT0()  asm volatile("cp.async.wait_group 0;" ::: "memory")

// ---------------------------------------------------------------------------
// Kernel 1: QKV projection via tf32 mma.sync (unchanged from R7).
// ---------------------------------------------------------------------------
__global__ __launch_bounds__(256) void qkv_mma_kernel(
    const float* __restrict__ x,
    const float* __restrict__ Wq,
    const float* __restrict__ Wk,
    const float* __restrict__ Wv)
{
    extern __shared__ float sm[];
    uint32_t* AsU = (uint32_t*)sm;
    uint32_t* BsU = (uint32_t*)(sm + G_AS_FLOATS);

    const int z  = blockIdx.z;
    const float* __restrict__ Wp = (z == 0) ? Wq : (z == 1) ? Wk : Wv;
    float* __restrict__ outp     = (z == 0) ? Qg : (z == 1) ? Kg : Vg;
    const int m0 = blockIdx.x * 128;
    const int h  = blockIdx.y;
    const int n0 = h * 128;

    const int tid  = threadIdx.x;
    const int warp = tid >> 5, lane = tid & 31;
    const int g = lane >> 2, tg = lane & 3;
    const int wm0 = (warp & 1) * 64;
    const int wn0 = (warp >> 1) * 32;

    float acc[4][4][4];
#pragma unroll
    for (int mi = 0; mi < 4; mi++)
#pragma unroll
        for (int ni = 0; ni < 4; ni++)
#pragma unroll
            for (int c = 0; c < 4; c++) acc[mi][ni][c] = 0.f;

    for (int kc = 0; kc < 4; kc++) {
        const int k0 = kc * 32;
#pragma unroll
        for (int i = 0; i < 4; i++) {
            int f = tid + i * 256;
            int row = f >> 3, s4 = f & 7;
            float4 v = *(const float4*)&x[(size_t)(m0 + row) * E_ + k0 + 4 * s4];
            AsU[row * GA_STR + 4 * s4 + 0] = f2tf32(v.x);
            AsU[row * GA_STR + 4 * s4 + 1] = f2tf32(v.y);
            AsU[row * GA_STR + 4 * s4 + 2] = f2tf32(v.z);
            AsU[row * GA_STR + 4 * s4 + 3] = f2tf32(v.w);
        }
#pragma unroll
        for (int i = 0; i < 4; i++) {
            int f = tid + i * 256;
            int kk = f >> 5, n4 = f & 31;
            float4 v = *(const float4*)&Wp[(size_t)(k0 + kk) * EH_ + n0 + 4 * n4];
            BsU[kk * GB_STR + 4 * n4 + 0] = f2tf32(v.x);
            BsU[kk * GB_STR + 4 * n4 + 1] = f2tf32(v.y);
            BsU[kk * GB_STR + 4 * n4 + 2] = f2tf32(v.z);
            BsU[kk * GB_STR + 4 * n4 + 3] = f2tf32(v.w);
        }
        __syncthreads();

#pragma unroll
        for (int ks = 0; ks < 4; ks++) {
            const int kb = 8 * ks;
            uint32_t a[4][4], b[4][2];
#pragma unroll
            for (int mi = 0; mi < 4; mi++) {
                int r = wm0 + 16 * mi + g;
                a[mi][0] = AsU[r * GA_STR + kb + tg];
                a[mi][1] = AsU[(r + 8) * GA_STR + kb + tg];
                a[mi][2] = AsU[r * GA_STR + kb + tg + 4];
                a[mi][3] = AsU[(r + 8) * GA_STR + kb + tg + 4];
            }
#pragma unroll
            for (int ni = 0; ni < 4; ni++) {
                int col = wn0 + 8 * ni + g;
                b[ni][0] = BsU[(kb + tg) * GB_STR + col];
                b[ni][1] = BsU[(kb + tg + 4) * GB_STR + col];
            }
#pragma unroll
            for (int mi = 0; mi < 4; mi++)
#pragma unroll
                for (int ni = 0; ni < 4; ni++)
                    mma_tf32(acc[mi][ni], a[mi], b[ni]);
        }
        __syncthreads();
    }

    const int b_ = m0 >> 11;
    const int t0 = m0 & 2047;
#pragma unroll
    for (int mi = 0; mi < 4; mi++) {
        int rl = wm0 + 16 * mi + g;
        size_t rbase = ((size_t)(b_ * H_ + h) * T_ + t0 + rl) * E_;
#pragma unroll
        for (int ni = 0; ni < 4; ni++) {
            int n = wn0 + 8 * ni + 2 * tg;
            *(float2*)&outp[rbase + n] =
                make_float2(acc[mi][ni][0], acc[mi][ni][1]);
            *(float2*)&outp[rbase + 8 * E_ + n] =
                make_float2(acc[mi][ni][2], acc[mi][ni][3]);
        }
    }
}

// ---------------------------------------------------------------------------
// Kernel 3: output projection, M-tile 64 -> 128 CTAs.
// ---------------------------------------------------------------------------
__global__ __launch_bounds__(256) void out_mma_kernel(
    const float* __restrict__ Wu,
    const float* __restrict__ bu,
    float* __restrict__ out)
{
    extern __shared__ float sm[];
    uint32_t* AsU = (uint32_t*)sm;                   // [64][36]
    uint32_t* BsU = (uint32_t*)(sm + G_AS2_FLOATS);  // [32][136]

    const int m0 = blockIdx.x * 64;
    const int tid  = threadIdx.x;
    const int warp = tid >> 5, lane = tid & 31;
    const int g = lane >> 2, tg = lane & 3;
    const int wm0 = (warp & 1) * 32;
    const int wn0 = (warp >> 1) * 32;

    float acc[2][4][4];
#pragma unroll
    for (int mi = 0; mi < 2; mi++)
#pragma unroll
        for (int ni = 0; ni < 4; ni++)
#pragma unroll
            for (int c = 0; c < 4; c++) acc[mi][ni][c] = 0.f;

    for (int kc = 0; kc < 32; kc++) {
        const int k0 = kc * 32;
#pragma unroll
        for (int i = 0; i < 2; i++) {
            int f = tid + i * 256;                  // 0..511
            int row = f >> 3, s4 = f & 7;
            float4 v = *(const float4*)&Og[(size_t)(m0 + row) * EH_ + k0 + 4 * s4];
            AsU[row * GA_STR + 4 * s4 + 0] = f2tf32(v.x);
            AsU[row * GA_STR + 4 * s4 + 1] = f2tf32(v.y);
            AsU[row * GA_STR + 4 * s4 + 2] = f2tf32(v.z);
            AsU[row * GA_STR + 4 * s4 + 3] = f2tf32(v.w);
        }
#pragma unroll
        for (int i = 0; i < 4; i++) {
            int f = tid + i * 256;
            int kk = f >> 5, n4 = f & 31;
            float4 v = *(const float4*)&Wu[(size_t)(k0 + kk) * E_ + 4 * n4];
            BsU[kk * GB_STR + 4 * n4 + 0] = f2tf32(v.x);
            BsU[kk * GB_STR + 4 * n4 + 1] = f2tf32(v.y);
            BsU[kk * GB_STR + 4 * n4 + 2] = f2tf32(v.z);
            BsU[kk * GB_STR + 4 * n4 + 3] = f2tf32(v.w);
        }
        __syncthreads();

#pragma unroll
        for (int ks = 0; ks < 4; ks++) {
            const int kb = 8 * ks;
            uint32_t a[2][4], b[4][2];
#pragma unroll
            for (int mi = 0; mi < 2; mi++) {
                int r = wm0 + 16 * mi + g;
                a[mi][0] = AsU[r * GA_STR + kb + tg];
                a[mi][1] = AsU[(r + 8) * GA_STR + kb + tg];
                a[mi][2] = AsU[r * GA_STR + kb + tg + 4];
                a[mi][3] = AsU[(r + 8) * GA_STR + kb + tg + 4];
            }
#pragma unroll
            for (int ni = 0; ni < 4; ni++) {
                int col = wn0 + 8 * ni + g;
                b[ni][0] = BsU[(kb + tg) * GB_STR + col];
                b[ni][1] = BsU[(kb + tg + 4) * GB_STR + col];
            }
#pragma unroll
            for (int mi = 0; mi < 2; mi++)
#pragma unroll
                for (int ni = 0; ni < 4; ni++)
                    mma_tf32(acc[mi][ni], a[mi], b[ni]);
        }
        __syncthreads();
    }

#pragma unroll
    for (int mi = 0; mi < 2; mi++) {
        int m = m0 + wm0 + 16 * mi + g;
#pragma unroll
        for (int ni = 0; ni < 4; ni++) {
            int n = wn0 + 8 * ni + 2 * tg;
            float2 bias = *(const float2*)&bu[n];
            *(float2*)&out[(size_t)m * E_ + n] =
                make_float2(acc[mi][ni][0] + bias.x, acc[mi][ni][1] + bias.y);
            *(float2*)&out[(size_t)(m + 8) * E_ + n] =
                make_float2(acc[mi][ni][2] + bias.x, acc[mi][ni][3] + bias.y);
        }
    }
}

// ---------------------------------------------------------------------------
// Attention softmax + PV. V in smem is RAW fp32 bits; convert at frag load
// (numerically identical to converting at store time).
// ---------------------------------------------------------------------------
__device__ __forceinline__ void attn_softmax_pv(
    float sacc[8][4], float& m1, float& m2, float& l1, float& l2,
    float o[16][4], uint32_t* Ps, const uint32_t* Vs, int r1, int g, int tg)
{
    float mt1 = -INFINITY, mt2 = -INFINITY;
#pragma unroll
    for (int ni = 0; ni < 8; ni++) {
        mt1 = fmaxf(mt1, fmaxf(sacc[ni][0], sacc[ni][1]));
        mt2 = fmaxf(mt2, fmaxf(sacc[ni][2], sacc[ni][3]));
    }
    mt1 = fmaxf(mt1, __shfl_xor_sync(0xffffffffu, mt1, 1));
    mt1 = fmaxf(mt1, __shfl_xor_sync(0xffffffffu, mt1, 2));
    mt2 = fmaxf(mt2, __shfl_xor_sync(0xffffffffu, mt2, 1));
    mt2 = fmaxf(mt2, __shfl_xor_sync(0xffffffffu, mt2, 2));
    float mn1 = fmaxf(m1, mt1), mn2 = fmaxf(m2, mt2);
    float al1 = (m1 == mn1) ? 1.f : __expf(m1 - mn1);
    float al2 = (m2 == mn2) ? 1.f : __expf(m2 - mn2);
    float me1 = (mn1 == -INFINITY) ? 0.f : mn1;
    float me2 = (mn2 == -INFINITY) ? 0.f : mn2;
    float ls1 = 0.f, ls2 = 0.f;
#pragma unroll
    for (int ni = 0; ni < 8; ni++) {
        float p0 = __expf(sacc[ni][0] - me1);
        float p1 = __expf(sacc[ni][1] - me1);
        float p2 = __expf(sacc[ni][2] - me2);
        float p3 = __expf(sacc[ni][3] - me2);
        ls1 += p0 + p1; ls2 += p2 + p3;
        uint32_t* pb = Ps + r1 * AP_STR + 8 * ni + 2 * tg;
        pb[0] = f2tf32(p0); pb[1] = f2tf32(p1);
        pb[8 * AP_STR] = f2tf32(p2); pb[8 * AP_STR + 1] = f2tf32(p3);
    }
    ls1 += __shfl_xor_sync(0xffffffffu, ls1, 1);
    ls1 += __shfl_xor_sync(0xffffffffu, ls1, 2);
    ls2 += __shfl_xor_sync(0xffffffffu, ls2, 1);
    ls2 += __shfl_xor_sync(0xffffffffu, ls2, 2);
    l1 = l1 * al1 + ls1; m1 = mn1;
    l2 = l2 * al2 + ls2; m2 = mn2;
#pragma unroll
    for (int ni = 0; ni < 16; ni++) {
        o[ni][0] *= al1; o[ni][1] *= al1;
        o[ni][2] *= al2; o[ni][3] *= al2;
    }
    __syncwarp();
#pragma unroll
    for (int kp = 0; kp < 8; kp++) {
        uint32_t a[4];
        const uint32_t* pb = Ps + r1 * AP_STR + 8 * kp;
        a[0] = pb[tg]; a[1] = pb[8 * AP_STR + tg];
        a[2] = pb[tg + 4]; a[3] = pb[8 * AP_STR + tg + 4];
#pragma unroll
        for (int ni = 0; ni < 16; ni++) {
            const uint32_t* vb = Vs + (8 * kp + tg) * AV_STR + 8 * ni + g;
            uint32_t b[2] = { f2tf32(__uint_as_float(vb[0])),
                              f2tf32(__uint_as_float(vb[4 * AV_STR])) };
            mma_tf32(o[ni], a, b);
        }
    }
    __syncwarp();   // all lanes done reading Ps before next tile overwrites
}

// ---------------------------------------------------------------------------
// Kernel 2: flash attention, cp.async double-buffered K/V, Q in registers.
// BM=128, BN=64, 256 threads, 1 CTA/SM (smem ~170KB).
// ---------------------------------------------------------------------------
__global__ __launch_bounds__(256, 1) void attn_kernel(const int* __restrict__ mask)
{
    extern __shared__ uint32_t smu[];
    uint32_t* KV = smu;                       // [K0 | V0 | K1 | V1], each ST_U32
    uint32_t* Ps = smu + 4 * ST_U32;          // [128][68]
    int* needb = (int*)(Ps + 128 * AP_STR);

    const int bh = blockIdx.y;
    const int qt = (gridDim.x - 1) - blockIdx.x;   // heavy blocks first
    const int q0 = qt * 128;
    const int tid = threadIdx.x;
    const int w = tid >> 5, lane = tid & 31;
    const int g = lane >> 2, tg = lane & 3;
    const int r1 = 16 * w + g;
    const int gq1 = q0 + r1, gq2 = gq1 + 8;

    const float* __restrict__ Qp = Qg + (size_t)bh * T_ * E_;
    const float* __restrict__ Kp = Kg + (size_t)bh * T_ * E_;
    const float* __restrict__ Vp = Vg + (size_t)bh * T_ * E_;

    const uint32_t kv_base = smem_u32addr(KV);

    // --- stage Q through KV[0..1] area (128x132), convert, pull frags to regs
    {
        uint32_t* QT = KV;
#pragma unroll
        for (int i = 0; i < 16; i++) {
            int f = tid + i * 256;
            int row = f >> 5, c4 = f & 31;
            float4 v = *(const float4*)&Qp[(size_t)(q0 + row) * E_ + 4 * c4];
            uint32_t* d = QT + row * AK_STR + 4 * c4;
            d[0] = f2tf32(v.x * S2_); d[1] = f2tf32(v.y * S2_);
            d[2] = f2tf32(v.z * S2_); d[3] = f2tf32(v.w * S2_);
        }
        __syncthreads();
    }
    uint32_t qf[16][4];
#pragma unroll
    for (int ks = 0; ks < 16; ks++) {
        const uint32_t* qb = KV + r1 * AK_STR + 8 * ks;
        qf[ks][0] = qb[tg];
        qf[ks][1] = qb[8 * AK_STR + tg];
        qf[ks][2] = qb[tg + 4];
        qf[ks][3] = qb[8 * AK_STR + tg + 4];
    }
    __syncthreads();   // done reading staging area before cp.async overwrites

    float o[16][4];
#pragma unroll
    for (int ni = 0; ni < 16; ni++)
#pragma unroll
        for (int c = 0; c < 4; c++) o[ni][c] = 0.f;

    float m1 = -INFINITY, m2 = -INFINITY, l1 = 0.f, l2 = 0.f;
    const int ntA = 2 * qt + 2;

    // per-thread load coordinates (8 chunks of 16B for each of K and V)
    const int lrow = tid >> 5;        // base row pattern handled in loop

    // prefetch tile 0 into stage 0
    {
        uint32_t kb = kv_base;
        uint32_t vb = kv_base + ST_U32 * 4;
#pragma unroll
        for (int i = 0; i < 8; i++) {
            int f = tid + i * 256;
            int row = f >> 5, c4 = f & 31;
            uint32_t off = (uint32_t)(row * AK_STR + 4 * c4) * 4;
            cpa16(kb + off, Kp + (size_t)row * E_ + 4 * c4);
            cpa16(vb + off, Vp + (size_t)row * E_ + 4 * c4);
        }
        CPA_COMMIT();
    }

    for (int kt = 0; kt < ntA; kt++) {
        const int s = kt & 1;
        const int kt0 = kt * 64;

        // issue loads for kt+1 into stage s^1 (safe: prev compute on s^1
        // finished before the trailing __syncthreads of iteration kt-1)
        if (kt + 1 < ntA) {
            const int nk0 = (kt + 1) * 64;
            uint32_t kb = kv_base + (uint32_t)(s ^ 1) * 2 * ST_U32 * 4;
            uint32_t vb = kb + ST_U32 * 4;
#pragma unroll
            for (int i = 0; i < 8; i++) {
                int f = tid + i * 256;
                int row = f >> 5, c4 = f & 31;
                uint32_t off = (uint32_t)(row * AK_STR + 4 * c4) * 4;
                cpa16(kb + off, Kp + (size_t)(nk0 + row) * E_ + 4 * c4);
                cpa16(vb + off, Vp + (size_t)(nk0 + row) * E_ + 4 * c4);
            }
        }
        CPA_COMMIT();
        CPA_WAIT1();           // tile kt's group complete
        __syncthreads();

        const uint32_t* Ks = KV + (uint32_t)s * 2 * ST_U32;
        const uint32_t* Vs = Ks + ST_U32;

        if (q0 + 16 * w + 15 >= kt0) {
            float sacc[8][4];
#pragma unroll
            for (int ni = 0; ni < 8; ni++)
#pragma unroll
                for (int c = 0; c < 4; c++) sacc[ni][c] = 0.f;

#pragma unroll
            for (int ks = 0; ks < 16; ks++) {
#pragma unroll
                for (int ni = 0; ni < 8; ni++) {
                    const uint32_t* kb = Ks + (8 * ni + g) * AK_STR + 8 * ks;
                    uint32_t b[2] = { f2tf32(__uint_as_float(kb[tg])),
                                      f2tf32(__uint_as_float(kb[tg + 4])) };
                    mma_tf32(sacc[ni], qf[ks], b);
                }
            }
            // causal + external mask (mask==0 -> -1e9 overrides causal -inf)
#pragma unroll
            for (int ni = 0; ni < 8; ni++) {
                int k1 = kt0 + 8 * ni + 2 * tg;
                int2 ma = *(const int2*)&mask[(size_t)gq1 * T_ + k1];
                int2 mb = *(const int2*)&mask[(size_t)gq2 * T_ + k1];
                if (k1 > gq1)     sacc[ni][0] = -INFINITY;
                if (k1 + 1 > gq1) sacc[ni][1] = -INFINITY;
                if (k1 > gq2)     sacc[ni][2] = -INFINITY;
                if (k1 + 1 > gq2) sacc[ni][3] = -INFINITY;
                if (ma.x == 0) sacc[ni][0] = -1e9f;
                if (ma.y == 0) sacc[ni][1] = -1e9f;
                if (mb.x == 0) sacc[ni][2] = -1e9f;
                if (mb.y == 0) sacc[ni][3] = -1e9f;
            }
            attn_softmax_pv(sacc, m1, m2, l1, l2, o, Ps, Vs, r1, g, tg);
        } else {
            // fully-future tile for this warp: matters only for dead rows
            unsigned anyd = __any_sync(0xffffffffu, (m1 < -1e8f) || (m2 < -1e8f));
            if (anyd) {
                float sacc[8][4];
#pragma unroll
                for (int ni = 0; ni < 8; ni++) {
                    int k1 = kt0 + 8 * ni + 2 * tg;
                    int2 ma = *(const int2*)&mask[(size_t)gq1 * T_ + k1];
                    int2 mb = *(const int2*)&mask[(size_t)gq2 * T_ + k1];
                    sacc[ni][0] = ma.x ? -INFINITY : -1e9f;
                    sacc[ni][1] = ma.y ? -INFINITY : -1e9f;
                    sacc[ni][2] = mb.x ? -INFINITY : -1e9f;
                    sacc[ni][3] = mb.y ? -INFINITY : -1e9f;
                }
                attn_softmax_pv(sacc, m1, m2, l1, l2, o, Ps, Vs, r1, g, tg);
            }
        }
        __syncthreads();   // everyone done reading stage s before reuse
    }

    // Phase B: fully-masked rows attend to future mask==0 positions
    __syncthreads();
    if (tid == 0) *needb = 0;
    __syncthreads();
    if ((m1 < -1e8f) || (m2 < -1e8f)) *needb = 1;
    __syncthreads();
    if (*needb) {
        for (int kt = ntA; kt < T_ / 64; kt++) {
            const int kt0 = kt * 64;
            __syncthreads();
            {
                uint32_t vb = kv_base + ST_U32 * 4;   // V stage 0
#pragma unroll
                for (int i = 0; i < 8; i++) {
                    int f = tid + i * 256;
                    int row = f >> 5, c4 = f & 31;
                    uint32_t off = (uint32_t)(row * AV_STR + 4 * c4) * 4;
                    cpa16(vb + off, Vp + (size_t)(kt0 + row) * E_ + 4 * c4);
                }
                CPA_COMMIT();
                CPA_WAIT0();
            }
            __syncthreads();
            const uint32_t* Vs = KV + ST_U32;
            unsigned anyd = __any_sync(0xffffffffu, (m1 < -1e8f) || (m2 < -1e8f));
            if (anyd) {
                float sacc[8][4];
#pragma unroll
                for (int ni = 0; ni < 8; ni++) {
                    int k1 = kt0 + 8 * ni + 2 * tg;
                    int2 ma = *(const int2*)&mask[(size_t)gq1 * T_ + k1];
                    int2 mb = *(const int2*)&mask[(size_t)gq2 * T_ + k1];
                    sacc[ni][0] = ma.x ? -INFINITY : -1e9f;
                    sacc[ni][1] = ma.y ? -INFINITY : -1e9f;
                    sacc[ni][2] = mb.x ? -INFINITY : -1e9f;
                    sacc[ni][3] = mb.y ? -INFINITY : -1e9f;
                }
                attn_softmax_pv(sacc, m1, m2, l1, l2, o, Ps, Vs, r1, g, tg);
            }
        }
    }

    // epilogue: normalize and write Og[b*t][h*e]
    float inv1 = 1.f / l1, inv2 = 1.f / l2;
    const int b = bh >> 3, h = bh & 7;
    size_t base1 = ((size_t)(b * T_ + gq1)) * EH_ + h * E_;
    size_t base2 = base1 + (size_t)8 * EH_;
#pragma unroll
    for (int ni = 0; ni < 16; ni++) {
        int col = 8 * ni + 2 * tg;
        *(float2*)&Og[base1 + col] = make_float2(o[ni][0] * inv1, o[ni][1] * inv1);
        *(float2*)&Og[base2 + col] = make_float2(o[ni][2] * inv2, o[ni][3] * inv2);
    }
    (void)lrow;
}

// ---------------------------------------------------------------------------
extern "C" void kernel_launch(void* const* d_in, const int* in_sizes, int n_in,
                              void* d_out, int out_size)
{
    const float* x   = (const float*)d_in[0];
    const int*  mask = (const int*)  d_in[1];
    const float* Wq  = (const float*)d_in[2];
    const float* Wk  = (const float*)d_in[3];
    const float* Wv  = (const float*)d_in[4];
    const float* Wu  = (const float*)d_in[5];
    const float* bu  = (const float*)d_in[6];
    float* out = (float*)d_out;

    cudaFuncSetAttribute(attn_kernel,
                         cudaFuncAttributeMaxDynamicSharedMemorySize, SMEM_ATTN);
    cudaFuncSetAttribute(qkv_mma_kernel,
                         cudaFuncAttributeMaxDynamicSharedMemorySize, SMEM_GEMM);
    cudaFuncSetAttribute(out_mma_kernel,
                         cudaFuncAttributeMaxDynamicSharedMemorySize, SMEM_OUT);

    qkv_mma_kernel<<<dim3(M_ / 128, H_, 3), 256, SMEM_GEMM>>>(x, Wq, Wk, Wv);
    attn_kernel<<<dim3(T_ / 128, BH_), 256, SMEM_ATTN>>>(mask);
    out_mma_kernel<<<dim3(M_ / 64, 1, 1), 256, SMEM_OUT>>>(Wu, bu, out);
}